// round 7
// baseline (speedup 1.0000x reference)
#include <cuda_runtime.h>
#include <math.h>

#define BN_SCALE 0.99999500003749972f

#define NB 8
#define NP 1024
#define NR (NB*NP)     // 8192 rows total
#define KNN 20

// ---------------- static scratch (no allocations allowed) ----------------
__device__ __align__(16) float g_dist[(size_t)NR * NP];   // 32MB; reused as h (8192x1024)
__device__ __align__(16) float g_cat [(size_t)NR * 512];  // x1|x2|x3|x4 concatenated
__device__ __align__(16) float g_Y   [(size_t)2 * NR * 256];  // Yn | Yc (z-batched)
__device__ float g_xx[NR];
__device__ int   g_idx[NR * KNN];
__device__ float g_pmax[16 * NB * 1024];
__device__ float g_psum[16 * NB * 1024];
__device__ float g_f [NB * 2048];
__device__ float g_f1[NB * 512];
__device__ float g_f2[NB * 256];

// ---------------- row sum of squares (layer 1 only) ----------------
__global__ void __launch_bounds__(256) rowsum_kernel(
        const float* __restrict__ X, int ld, int C, float* __restrict__ xx) {
    int r = blockIdx.x * blockDim.x + threadIdx.x;
    if (r >= NR) return;
    const float* p = X + (size_t)r * ld;
    float s = 0.f;
    for (int c = 0; c < C; c++) s += p[c] * p[c];
    xx[r] = s;
}

// ---------------- fp32 NT GEMM (layer-1 K=3 only) ----------------
// mode 0: plain   mode 1: dist (2*acc - xx[m] - xx[n])
__global__ void __launch_bounds__(256) gemm_nt(int mode,
                        const float* __restrict__ A, int lda, int batA,
                        const float* __restrict__ B, int ldb, int batB,
                        float* __restrict__ C, int ldc, int batC, int K,
                        const float* __restrict__ xx, int batX)
{
    A += (size_t)blockIdx.z * batA;
    B += (size_t)blockIdx.z * batB;
    C += (size_t)blockIdx.z * batC;
    const int m0 = blockIdx.y * 64;
    const int n0 = blockIdx.x * 64;
    __shared__ __align__(16) float As[16][64];
    __shared__ __align__(16) float Bs[16][64];
    const int tx = threadIdx.x, ty = threadIdx.y;
    const int t = ty * 16 + tx;
    const int lm = t >> 2;
    const int lk = (t & 3) * 4;
    float acc[4][4] = {};
    for (int k0 = 0; k0 < K; k0 += 16) {
        #pragma unroll
        for (int u = 0; u < 4; u++) {
            int kk = lk + u;
            As[kk][lm] = (k0 + kk < K) ? A[(size_t)(m0 + lm) * lda + k0 + kk] : 0.f;
            Bs[kk][lm] = (k0 + kk < K) ? B[(size_t)(n0 + lm) * ldb + k0 + kk] : 0.f;
        }
        __syncthreads();
        #pragma unroll
        for (int kk = 0; kk < 16; kk++) {
            float4 a4 = *reinterpret_cast<const float4*>(&As[kk][ty * 4]);
            float4 b4 = *reinterpret_cast<const float4*>(&Bs[kk][tx * 4]);
            float a[4] = {a4.x, a4.y, a4.z, a4.w};
            float b[4] = {b4.x, b4.y, b4.z, b4.w};
            #pragma unroll
            for (int i = 0; i < 4; i++)
                #pragma unroll
                for (int j = 0; j < 4; j++)
                    acc[i][j] = fmaf(a[i], b[j], acc[i][j]);
        }
        __syncthreads();
    }
    #pragma unroll
    for (int i = 0; i < 4; i++) {
        int m = m0 + ty * 4 + i;
        int n = n0 + tx * 4;
        float4 v; float* vp = &v.x;
        if (mode == 1) {
            float xm = xx[batX * blockIdx.z + m];
            #pragma unroll
            for (int j = 0; j < 4; j++)
                vp[j] = 2.f * acc[i][j] - xm - xx[batX * blockIdx.z + n + j];
        } else {
            #pragma unroll
            for (int j = 0; j < 4; j++) vp[j] = acc[i][j];
        }
        *reinterpret_cast<float4*>(&C[(size_t)m * ldc + n]) = v;
    }
}

// ---------------- split-tf32 tensor-core NT GEMM (3xTF32, ~fp32 accuracy) ----------------
// C(MxN) = A(MxK,row) * B(NxK,row)^T ; K%16==0, M%128==0.
// Block 128x128, 8 warps 2(m)x4(n), warp tile 64x32, mma m16n8k8.
// Split to hi/lo at STS (once per element); register-prefetch double buffering.
// sym=1 (with mode 1): compute lower triangle only, mirror via smem transpose.
__device__ __forceinline__ unsigned f2tf(float f) {
    unsigned u; asm("cvt.rna.tf32.f32 %0, %1;" : "=r"(u) : "f"(f)); return u;
}
__device__ __forceinline__ void split_store(unsigned* hi, unsigned* lo, float4 v) {
    unsigned hx = f2tf(v.x), hy = f2tf(v.y), hz = f2tf(v.z), hw = f2tf(v.w);
    uint4 H = {hx, hy, hz, hw};
    uint4 L = {f2tf(v.x - __uint_as_float(hx)), f2tf(v.y - __uint_as_float(hy)),
               f2tf(v.z - __uint_as_float(hz)), f2tf(v.w - __uint_as_float(hw))};
    *(uint4*)hi = H;
    *(uint4*)lo = L;
}
#define MMA_TF32(c, a0,a1,a2,a3, b0,b1)                                        \
    asm volatile("mma.sync.aligned.m16n8k8.row.col.f32.tf32.tf32.f32 "          \
                 "{%0,%1,%2,%3}, {%4,%5,%6,%7}, {%8,%9}, {%0,%1,%2,%3};"        \
                 : "+f"(c[0]), "+f"(c[1]), "+f"(c[2]), "+f"(c[3])               \
                 : "r"(a0), "r"(a1), "r"(a2), "r"(a3), "r"(b0), "r"(b1))

__global__ void __launch_bounds__(256) gemm_tf32(int mode, int N, int sym,
        const float* __restrict__ A, int lda, int batA,
        const float* __restrict__ B, int ldb, int batB,
        float* __restrict__ C, int ldc, int batC, int K,
        const float* __restrict__ xx, int batX,
        const float* __restrict__ gg, const float* __restrict__ bb)
{
    if (sym && blockIdx.x > blockIdx.y) return;   // lower triangle only
    A += (size_t)blockIdx.z * batA;
    B += (size_t)blockIdx.z * batB;
    C += (size_t)blockIdx.z * batC;
    const float* xb = xx ? (xx + (size_t)batX * blockIdx.z) : xx;

    const int m0 = blockIdx.y * 128;
    const int n0 = blockIdx.x * 128;

    // [hi/lo][row][k], stride 20 -> conflict-free frag loads. 40KB, contiguous per matrix.
    __shared__ __align__(16) unsigned Ahl[2][128][20];
    __shared__ __align__(16) unsigned Bhl[2][128][20];

    const int tid = threadIdx.x;
    const int w  = tid >> 5, l = tid & 31;
    const int g  = l >> 2,  t4 = l & 3;
    const int wm = (w & 1) * 64;
    const int wn = (w >> 1) * 32;
    const int lr = tid >> 2;          // 0..63
    const int lk = (tid & 3) * 4;     // 0,4,8,12

    float c[4][4][4];
    #pragma unroll
    for (int i = 0; i < 4; i++)
        #pragma unroll
        for (int j = 0; j < 4; j++)
            #pragma unroll
            for (int q = 0; q < 4; q++) c[i][j][q] = 0.f;

    const float4 z4 = {0.f, 0.f, 0.f, 0.f};
    float4 ra0, ra1, rb0, rb1;

    // prologue: load k-tile 0 into registers
    {
        const float* Ap = A + (size_t)(m0 + lr) * lda + lk;
        ra0 = *(const float4*)Ap;
        ra1 = *(const float4*)(Ap + (size_t)64 * lda);
        int nr0 = n0 + lr, nr1 = nr0 + 64;
        rb0 = (nr0 < N) ? *(const float4*)(B + (size_t)nr0 * ldb + lk) : z4;
        rb1 = (nr1 < N) ? *(const float4*)(B + (size_t)nr1 * ldb + lk) : z4;
    }

    const int T = K / 16;
    for (int t = 0; t < T; t++) {
        __syncthreads();   // previous tile's mma done reading smem
        split_store(&Ahl[0][lr][lk],      &Ahl[1][lr][lk],      ra0);
        split_store(&Ahl[0][lr + 64][lk], &Ahl[1][lr + 64][lk], ra1);
        split_store(&Bhl[0][lr][lk],      &Bhl[1][lr][lk],      rb0);
        split_store(&Bhl[0][lr + 64][lk], &Bhl[1][lr + 64][lk], rb1);
        __syncthreads();
        if (t + 1 < T) {   // prefetch next tile, overlapped with mma below
            int k0 = (t + 1) * 16;
            const float* Ap = A + (size_t)(m0 + lr) * lda + k0 + lk;
            ra0 = *(const float4*)Ap;
            ra1 = *(const float4*)(Ap + (size_t)64 * lda);
            int nr0 = n0 + lr, nr1 = nr0 + 64;
            rb0 = (nr0 < N) ? *(const float4*)(B + (size_t)nr0 * ldb + k0 + lk) : z4;
            rb1 = (nr1 < N) ? *(const float4*)(B + (size_t)nr1 * ldb + k0 + lk) : z4;
        }
        #pragma unroll
        for (int kk = 0; kk < 16; kk += 8) {
            unsigned ah[4][4], al[4][4], bh[4][2], bl[4][2];
            #pragma unroll
            for (int mi = 0; mi < 4; mi++) {
                int r = wm + mi * 16 + g;
                ah[mi][0] = Ahl[0][r    ][kk + t4];
                ah[mi][1] = Ahl[0][r + 8][kk + t4];
                ah[mi][2] = Ahl[0][r    ][kk + t4 + 4];
                ah[mi][3] = Ahl[0][r + 8][kk + t4 + 4];
                al[mi][0] = Ahl[1][r    ][kk + t4];
                al[mi][1] = Ahl[1][r + 8][kk + t4];
                al[mi][2] = Ahl[1][r    ][kk + t4 + 4];
                al[mi][3] = Ahl[1][r + 8][kk + t4 + 4];
            }
            #pragma unroll
            for (int ni = 0; ni < 4; ni++) {
                int r = wn + ni * 8 + g;
                bh[ni][0] = Bhl[0][r][kk + t4];
                bh[ni][1] = Bhl[0][r][kk + t4 + 4];
                bl[ni][0] = Bhl[1][r][kk + t4];
                bl[ni][1] = Bhl[1][r][kk + t4 + 4];
            }
            #pragma unroll
            for (int mi = 0; mi < 4; mi++)
                #pragma unroll
                for (int ni = 0; ni < 4; ni++) {
                    float* cc = c[mi][ni];
                    MMA_TF32(cc, ah[mi][0], ah[mi][1], ah[mi][2], ah[mi][3],
                                 bl[ni][0], bl[ni][1]);
                    MMA_TF32(cc, al[mi][0], al[mi][1], al[mi][2], al[mi][3],
                                 bh[ni][0], bh[ni][1]);
                    MMA_TF32(cc, ah[mi][0], ah[mi][1], ah[mi][2], ah[mi][3],
                                 bh[ni][0], bh[ni][1]);
                }
        }
    }

    // ---- normal epilogue ----
    #pragma unroll
    for (int mi = 0; mi < 4; mi++) {
        int r0 = m0 + wm + mi * 16 + g;
        int r1 = r0 + 8;
        float xm0 = 0.f, xm1 = 0.f;
        if (mode == 1) { xm0 = xb[r0]; xm1 = xb[r1]; }
        #pragma unroll
        for (int ni = 0; ni < 4; ni++) {
            int n = n0 + wn + ni * 8 + t4 * 2;
            if (n < N) {
                float v0 = c[mi][ni][0], v1 = c[mi][ni][1];
                float v2 = c[mi][ni][2], v3 = c[mi][ni][3];
                if (mode == 1) {
                    float xn0 = xb[n], xn1 = xb[n + 1];
                    v0 = 2.f * v0 - xm0 - xn0;  v1 = 2.f * v1 - xm0 - xn1;
                    v2 = 2.f * v2 - xm1 - xn0;  v3 = 2.f * v3 - xm1 - xn1;
                } else if (mode == 2) {
                    float s0 = gg[n] * BN_SCALE, s1 = gg[n + 1] * BN_SCALE;
                    float b0v = bb[n], b1v = bb[n + 1];
                    v0 = fmaf(s0, v0, b0v); v0 = (v0 > 0.f) ? v0 : expm1f(v0);
                    v1 = fmaf(s1, v1, b1v); v1 = (v1 > 0.f) ? v1 : expm1f(v1);
                    v2 = fmaf(s0, v2, b0v); v2 = (v2 > 0.f) ? v2 : expm1f(v2);
                    v3 = fmaf(s1, v3, b1v); v3 = (v3 > 0.f) ? v3 : expm1f(v3);
                }
                float2 p0 = {v0, v1}, p1 = {v2, v3};
                *(float2*)&C[(size_t)r0 * ldc + n] = p0;
                *(float2*)&C[(size_t)r1 * ldc + n] = p1;
            }
        }
    }

    // ---- mirror epilogue (sym, strictly lower blocks): C[n][m] via smem transpose ----
    // stride 132 floats = 528B (multiple of 16B) keeps float4 accesses aligned.
    if (sym && blockIdx.x < blockIdx.y) {
        float (*st)[132] = reinterpret_cast<float(*)[132]>(&Ahl[0][0][0]); // 16.9KB < 20.5KB
        #pragma unroll 1
        for (int s = 0; s < 4; s++) {    // s = ni strip; covers 32 mirror rows
            __syncthreads();
            #pragma unroll
            for (int mi = 0; mi < 4; mi++) {
                int r0l = wm + mi * 16 + g;       // local row 0..127
                int r0 = m0 + r0l, r1 = r0 + 8;
                int n  = n0 + wn + s * 8 + t4 * 2;
                float xm0 = xb[r0], xm1 = xb[r1];
                float xn0 = xb[n],  xn1 = xb[n + 1];
                float v0 = 2.f * c[mi][s][0] - xm0 - xn0;
                float v1 = 2.f * c[mi][s][1] - xm0 - xn1;
                float v2 = 2.f * c[mi][s][2] - xm1 - xn0;
                float v3 = 2.f * c[mi][s][3] - xm1 - xn1;
                int cl = (w >> 1) * 8 + t4 * 2;   // strip-local col 0..31
                st[cl    ][r0l]     = v0;
                st[cl + 1][r0l]     = v1;
                st[cl    ][r0l + 8] = v2;
                st[cl + 1][r0l + 8] = v3;
            }
            __syncthreads();
            int rsel = tid >> 3;                   // 0..31
            int wnq = rsel >> 3, off = rsel & 7;
            int nl = wnq * 32 + s * 8 + off;       // tile-local col = mirror row
            int colm = (tid & 7) * 16;
            float* dst = &C[(size_t)(n0 + nl) * ldc + m0 + colm];
            const float* src = &st[rsel][colm];
            #pragma unroll
            for (int q = 0; q < 4; q++)
                *(float4*)(dst + q * 4) = *(const float4*)(src + q * 4);
        }
    }
}

// ---------------- top-k (k=20): u64 keys, cached top-3 tournament ----------------
// key = ordered(val)<<32 | (1023-idx): larger key = larger val, ties -> lower idx.
__global__ void __launch_bounds__(256) topk_kernel(
        const float* __restrict__ D, int* __restrict__ out) {
    int warp = (blockIdx.x * blockDim.x + threadIdx.x) >> 5;
    int lane = threadIdx.x & 31;
    const float* row = D + (size_t)warp * NP;
    unsigned long long k[32];
    #pragma unroll
    for (int j = 0; j < 32; j++) {
        int idx = lane + j * 32;
        unsigned u = __float_as_uint(row[idx]);
        unsigned o = (u & 0x80000000u) ? ~u : (u | 0x80000000u);
        k[j] = ((unsigned long long)o << 32) | (unsigned)(1023 - idx);
    }
    int base = warp & ~(NP - 1);   // batch base as global row
    unsigned long long s0 = 0, s1 = 0, s2 = 0;
    // initial top-3
    #pragma unroll
    for (int j = 0; j < 32; j++) {
        unsigned long long x = k[j];
        if (x > s0)      { s2 = s1; s1 = s0; s0 = x; }
        else if (x > s1) { s2 = s1; s1 = x; }
        else if (x > s2) { s2 = x; }
    }
    for (int it = 0; it < KNN; it++) {
        unsigned long long wv = s0;
        #pragma unroll
        for (int off = 16; off; off >>= 1) {
            unsigned long long o = __shfl_xor_sync(0xffffffffu, wv, off);
            if (o > wv) wv = o;
        }
        if (s0 == wv) {          // unique winner pops
            s0 = s1; s1 = s2; s2 = 0;
            if (s0 == 0) {       // cache exhausted: refill top-3 among keys < wv
                #pragma unroll
                for (int j = 0; j < 32; j++) {
                    unsigned long long x = k[j];
                    if (x < wv) {
                        if (x > s0)      { s2 = s1; s1 = s0; s0 = x; }
                        else if (x > s1) { s2 = s1; s1 = x; }
                        else if (x > s2) { s2 = x; }
                    }
                }
            }
        }
        if (lane == 0) out[warp * KNN + it] = base + 1023 - (int)(wv & 1023u);
    }
}

// ---------------- edge-conv aggregation (+ fused rowsum for next layer) ----------------
__global__ void __launch_bounds__(256) aggregate_kernel(
        const float* __restrict__ Yn, const float* __restrict__ Yc,
        int C, const int* __restrict__ idx,
        const float* __restrict__ gg, const float* __restrict__ bb,
        float* __restrict__ outp /* = g_cat + off, ld 512 */,
        float* __restrict__ xxout) {
    int r = blockIdx.x;
    int c = threadIdx.x;
    __shared__ int sidx[KNN];
    __shared__ float red[256];
    if (c < KNN) sidx[c] = idx[r * KNN + c];
    __syncthreads();
    float vmax = -INFINITY, vmin = INFINITY;
    #pragma unroll 4
    for (int j = 0; j < KNN; j++) {
        float v = Yn[(size_t)sidx[j] * C + c];
        vmax = fmaxf(vmax, v);
        vmin = fminf(vmin, v);
    }
    float center = Yc[(size_t)r * C + c] - Yn[(size_t)r * C + c];
    float s = gg[c] * BN_SCALE;
    float h = s * ((s >= 0.f ? vmax : vmin) + center) + bb[c];
    float e = (h > 0.f) ? h : expm1f(h);
    outp[(size_t)r * 512 + c] = e;
    if (xxout) {
        red[c] = e * e;
        __syncthreads();
        for (int st = blockDim.x >> 1; st > 0; st >>= 1) {
            if (c < st) red[c] += red[c + st];
            __syncthreads();
        }
        if (c == 0) xxout[r] = red[0];
    }
}

// ---------------- global max/mean pooling ----------------
__global__ void __launch_bounds__(256) pool_partial(
        const float* __restrict__ h,
        float* __restrict__ pmax, float* __restrict__ psum) {
    int o  = blockIdx.y * 256 + threadIdx.x;
    int b  = blockIdx.x;
    int nz = blockIdx.z;
    float m = -INFINITY, s = 0.f;
    for (int n = nz * 64; n < nz * 64 + 64; n++) {
        float v = h[((size_t)(b * NP + n)) * 1024 + o];
        m = fmaxf(m, v); s += v;
    }
    pmax[(nz * NB + b) * 1024 + o] = m;
    psum[(nz * NB + b) * 1024 + o] = s;
}

__global__ void __launch_bounds__(256) pool_combine(
        const float* __restrict__ pmax, const float* __restrict__ psum,
        float* __restrict__ f) {
    int t = blockIdx.x * 256 + threadIdx.x;
    if (t >= NB * 1024) return;
    int b = t >> 10, o = t & 1023;
    float m = -INFINITY, s = 0.f;
    for (int c = 0; c < 16; c++) {
        m = fmaxf(m, pmax[(c * NB + b) * 1024 + o]);
        s += psum[(c * NB + b) * 1024 + o];
    }
    f[b * 2048 + o] = m;
    f[b * 2048 + 1024 + o] = s * (1.f / 1024.f);
}

// ---------------- tiny MLP: one warp per output element ----------------
__global__ void __launch_bounds__(256) mlp_kernel(
        const float* __restrict__ in, int Kd,
        const float* __restrict__ W,
        const float* __restrict__ gg, const float* __restrict__ bb,
        float* __restrict__ out, int Nout, int rows, int bnelu) {
    int wid  = (blockIdx.x * blockDim.x + threadIdx.x) >> 5;
    int lane = threadIdx.x & 31;
    if (wid >= rows * Nout) return;
    int r = wid / Nout, o = wid % Nout;
    const float* a = in + (size_t)r * Kd;
    const float* w = W  + (size_t)o * Kd;
    float s = 0.f;
    for (int k = lane; k < Kd; k += 32) s += a[k] * w[k];
    #pragma unroll
    for (int off = 16; off; off >>= 1) s += __shfl_xor_sync(0xffffffffu, s, off);
    if (lane == 0) {
        float v;
        if (bnelu) {
            float sc = gg[o] * BN_SCALE;
            v = fmaf(sc, s, bb[o]);
            v = (v > 0.f) ? v : expm1f(v);
        } else {
            v = s + bb[o];
        }
        out[(size_t)r * Nout + o] = v;
    }
}

extern "C" void kernel_launch(void* const* d_in, const int* in_sizes, int n_in,
                              void* d_out, int out_size) {
    const float* x   = (const float*)d_in[0];
    const float* W1  = (const float*)d_in[1];
    const float* g1  = (const float*)d_in[2];
    const float* b1  = (const float*)d_in[3];
    const float* W2  = (const float*)d_in[4];
    const float* g2  = (const float*)d_in[5];
    const float* b2  = (const float*)d_in[6];
    const float* W3  = (const float*)d_in[7];
    const float* g3  = (const float*)d_in[8];
    const float* b3  = (const float*)d_in[9];
    const float* W4  = (const float*)d_in[10];
    const float* g4  = (const float*)d_in[11];
    const float* b4  = (const float*)d_in[12];
    const float* W5  = (const float*)d_in[13];
    const float* g5  = (const float*)d_in[14];
    const float* b5  = (const float*)d_in[15];
    const float* Wl1 = (const float*)d_in[16];
    const float* gl1 = (const float*)d_in[17];
    const float* bl1 = (const float*)d_in[18];
    const float* Wl2 = (const float*)d_in[19];
    const float* gl2 = (const float*)d_in[20];
    const float* bl2 = (const float*)d_in[21];
    const float* Wl3 = (const float*)d_in[22];
    const float* bl3 = (const float*)d_in[23];

    float *dist, *cat, *Y, *xx, *pmax, *psum, *f, *f1, *f2;
    int* idx;
    cudaGetSymbolAddress((void**)&dist, g_dist);
    cudaGetSymbolAddress((void**)&cat,  g_cat);
    cudaGetSymbolAddress((void**)&Y,    g_Y);
    cudaGetSymbolAddress((void**)&xx,   g_xx);
    cudaGetSymbolAddress((void**)&idx,  g_idx);
    cudaGetSymbolAddress((void**)&pmax, g_pmax);
    cudaGetSymbolAddress((void**)&psum, g_psum);
    cudaGetSymbolAddress((void**)&f,    g_f);
    cudaGetSymbolAddress((void**)&f1,   g_f1);
    cudaGetSymbolAddress((void**)&f2,   g_f2);

    dim3 blk(16, 16);

    // ---------- layer 1 (fp32, K=3) ----------
    rowsum_kernel<<<NR / 256, 256>>>(x, 3, 3, xx);
    gemm_nt<<<dim3(NP / 64, NP / 64, NB), blk>>>(1, x, 3, NP * 3, x, 3, NP * 3,
                                                 dist, NP, NP * NP, 3, xx, NP);
    topk_kernel<<<NR / 8, 256>>>(dist, idx);
    // merged Yn/Yc: z=0 -> Wd, z=1 -> Wc
    gemm_nt<<<dim3(1, NR / 64, 2), blk>>>(0, x, 3, 0, W1, 6, 3,
                                          Y, 64, NR * 64, 3, nullptr, 0);
    aggregate_kernel<<<NR, 64>>>(Y, Y + (size_t)NR * 64, 64, idx, g1, b1, cat + 0, xx);

    // ---------- layers 2-4 (split-tf32) ----------
    struct { const float* X; int Cin; const float* W; const float* g; const float* b;
             int Cout; int off; } L[3] = {
        { cat + 0,   64,  W2, g2, b2,  64,  64 },
        { cat + 64,  64,  W3, g3, b3, 128, 128 },
        { cat + 128, 128, W4, g4, b4, 256, 256 },
    };
    for (int li = 0; li < 3; li++) {
        // symmetric dist (xx from previous aggregate)
        gemm_tf32<<<dim3(NP / 128, NP / 128, NB), 256>>>(1, NP, 1,
            L[li].X, 512, NP * 512, L[li].X, 512, NP * 512,
            dist, NP, NP * NP, L[li].Cin, xx, NP, nullptr, nullptr);
        topk_kernel<<<NR / 8, 256>>>(dist, idx);
        // merged Yn/Yc via z
        gemm_tf32<<<dim3((L[li].Cout + 127) / 128, NR / 128, 2), 256>>>(0, L[li].Cout, 0,
            L[li].X, 512, 0, L[li].W, 2 * L[li].Cin, L[li].Cin,
            Y, L[li].Cout, NR * L[li].Cout, L[li].Cin, nullptr, 0, nullptr, nullptr);
        aggregate_kernel<<<NR, L[li].Cout>>>(Y, Y + (size_t)NR * L[li].Cout,
            L[li].Cout, idx, L[li].g, L[li].b, cat + L[li].off,
            (li < 2) ? xx : nullptr);
    }

    // ---------- conv5: h = elu(bn(cat @ W5^T)), reuse dist as h ----------
    gemm_tf32<<<dim3(1024 / 128, NR / 128, 1), 256>>>(2, 1024, 0,
        cat, 512, 0, W5, 512, 0,
        dist, 1024, 0, 512, nullptr, 0, g5, b5);

    // ---------- pooling + MLP head ----------
    pool_partial<<<dim3(NB, 4, 16), 256>>>(dist, pmax, psum);
    pool_combine<<<32, 256>>>(pmax, psum, f);
    mlp_kernel<<<512, 256>>>(f,  2048, Wl1, gl1, bl1, f1, 512, NB, 1);
    mlp_kernel<<<256, 256>>>(f1, 512,  Wl2, gl2, bl2, f2, 256, NB, 1);
    mlp_kernel<<<40,  256>>>(f2, 256,  Wl3, nullptr, bl3, (float*)d_out, 40, NB, 0);
}

// round 8
// speedup vs baseline: 1.0506x; 1.0506x over previous
#include <cuda_runtime.h>
#include <math.h>

#define BN_SCALE 0.99999500003749972f

#define NB 8
#define NP 1024
#define NR (NB*NP)     // 8192 rows total
#define KNN 20

// ---------------- static scratch (no allocations allowed) ----------------
__device__ __align__(16) float g_dist[(size_t)NR * NP];   // 32MB; reused as h (8192x1024)
__device__ __align__(16) float g_cat [(size_t)NR * 512];  // x1|x2|x3|x4 concatenated
__device__ __align__(16) float g_Y   [(size_t)2 * NR * 256];  // Yn | Yc (z-batched)
__device__ float g_xx[NR];
__device__ int   g_idx[NR * KNN];
__device__ float g_pmax[16 * NB * 1024];
__device__ float g_psum[16 * NB * 1024];
__device__ float g_f [NB * 2048];
__device__ float g_f1[NB * 512];
__device__ float g_f2[NB * 256];

// ---------------- row sum of squares (layer 1 only) ----------------
__global__ void __launch_bounds__(256) rowsum_kernel(
        const float* __restrict__ X, int ld, int C, float* __restrict__ xx) {
    int r = blockIdx.x * blockDim.x + threadIdx.x;
    if (r >= NR) return;
    const float* p = X + (size_t)r * ld;
    float s = 0.f;
    for (int c = 0; c < C; c++) s += p[c] * p[c];
    xx[r] = s;
}

// ---------------- fp32 NT GEMM (layer-1 K=3 only) ----------------
// mode 0: plain   mode 1: dist (2*acc - xx[m] - xx[n])
__global__ void __launch_bounds__(256) gemm_nt(int mode,
                        const float* __restrict__ A, int lda, int batA,
                        const float* __restrict__ B, int ldb, int batB,
                        float* __restrict__ C, int ldc, int batC, int K,
                        const float* __restrict__ xx, int batX)
{
    A += (size_t)blockIdx.z * batA;
    B += (size_t)blockIdx.z * batB;
    C += (size_t)blockIdx.z * batC;
    const int m0 = blockIdx.y * 64;
    const int n0 = blockIdx.x * 64;
    __shared__ __align__(16) float As[16][64];
    __shared__ __align__(16) float Bs[16][64];
    const int tx = threadIdx.x, ty = threadIdx.y;
    const int t = ty * 16 + tx;
    const int lm = t >> 2;
    const int lk = (t & 3) * 4;
    float acc[4][4] = {};
    for (int k0 = 0; k0 < K; k0 += 16) {
        #pragma unroll
        for (int u = 0; u < 4; u++) {
            int kk = lk + u;
            As[kk][lm] = (k0 + kk < K) ? A[(size_t)(m0 + lm) * lda + k0 + kk] : 0.f;
            Bs[kk][lm] = (k0 + kk < K) ? B[(size_t)(n0 + lm) * ldb + k0 + kk] : 0.f;
        }
        __syncthreads();
        #pragma unroll
        for (int kk = 0; kk < 16; kk++) {
            float4 a4 = *reinterpret_cast<const float4*>(&As[kk][ty * 4]);
            float4 b4 = *reinterpret_cast<const float4*>(&Bs[kk][tx * 4]);
            float a[4] = {a4.x, a4.y, a4.z, a4.w};
            float b[4] = {b4.x, b4.y, b4.z, b4.w};
            #pragma unroll
            for (int i = 0; i < 4; i++)
                #pragma unroll
                for (int j = 0; j < 4; j++)
                    acc[i][j] = fmaf(a[i], b[j], acc[i][j]);
        }
        __syncthreads();
    }
    #pragma unroll
    for (int i = 0; i < 4; i++) {
        int m = m0 + ty * 4 + i;
        int n = n0 + tx * 4;
        float4 v; float* vp = &v.x;
        if (mode == 1) {
            float xm = xx[batX * blockIdx.z + m];
            #pragma unroll
            for (int j = 0; j < 4; j++)
                vp[j] = 2.f * acc[i][j] - xm - xx[batX * blockIdx.z + n + j];
        } else {
            #pragma unroll
            for (int j = 0; j < 4; j++) vp[j] = acc[i][j];
        }
        *reinterpret_cast<float4*>(&C[(size_t)m * ldc + n]) = v;
    }
}

// ---------------- split-tf32 tensor-core NT GEMM (3xTF32, ~fp32 accuracy) ----------------
// C(MxN) = A(MxK,row) * B(NxK,row)^T ; K%16==0, M%128==0.
// Block 128x128, 8 warps 2(m)x4(n), warp tile 64x32, mma m16n8k8.
// fp32 tiles in smem (double-buffered, cp.async); Markidis mask-split at frag load
// (LOP3 on ALU pipe + 1 FSUB, no cvt on the FMA pipe).
// sym=1 (with mode 1): compute lower triangle only, mirror via smem transpose.
__device__ __forceinline__ void spl(float f, unsigned& hi, unsigned& lo) {
    hi = __float_as_uint(f) & 0xFFFFE000u;                       // LOP3 (ALU)
    lo = __float_as_uint(f - __uint_as_float(hi)) & 0xFFFFE000u; // FSUB (FMA) + LOP3 (ALU)
}
__device__ __forceinline__ void cp16(void* dst, const void* src, int sz) {
    unsigned d = (unsigned)__cvta_generic_to_shared(dst);
    asm volatile("cp.async.ca.shared.global [%0], [%1], 16, %2;"
                 :: "r"(d), "l"(src), "r"(sz));
}
#define MMA_TF32(c, a0,a1,a2,a3, b0,b1)                                        \
    asm volatile("mma.sync.aligned.m16n8k8.row.col.f32.tf32.tf32.f32 "          \
                 "{%0,%1,%2,%3}, {%4,%5,%6,%7}, {%8,%9}, {%0,%1,%2,%3};"        \
                 : "+f"(c[0]), "+f"(c[1]), "+f"(c[2]), "+f"(c[3])               \
                 : "r"(a0), "r"(a1), "r"(a2), "r"(a3), "r"(b0), "r"(b1))

__global__ void __launch_bounds__(256) gemm_tf32(int mode, int N, int sym,
        const float* __restrict__ A, int lda, int batA,
        const float* __restrict__ B, int ldb, int batB,
        float* __restrict__ C, int ldc, int batC, int K,
        const float* __restrict__ xx, int batX,
        const float* __restrict__ gg, const float* __restrict__ bb)
{
    if (sym && blockIdx.x > blockIdx.y) return;   // lower triangle only
    A += (size_t)blockIdx.z * batA;
    B += (size_t)blockIdx.z * batB;
    C += (size_t)blockIdx.z * batC;
    const float* xb = xx ? (xx + (size_t)batX * blockIdx.z) : xx;

    const int m0 = blockIdx.y * 128;
    const int n0 = blockIdx.x * 128;

    __shared__ __align__(16) float As[2][128][20];   // fp32 tiles, 20KB
    __shared__ __align__(16) float Bs[2][128][20];   // 20KB

    const int tid = threadIdx.x;
    const int w  = tid >> 5, l = tid & 31;
    const int g  = l >> 2,  t4 = l & 3;
    const int wm = (w & 1) * 64;
    const int wn = (w >> 1) * 32;
    const int lr = tid >> 2;          // 0..63
    const int lk = (tid & 3) * 4;     // 0,4,8,12

    float c[4][4][4];
    #pragma unroll
    for (int i = 0; i < 4; i++)
        #pragma unroll
        for (int j = 0; j < 4; j++)
            #pragma unroll
            for (int q = 0; q < 4; q++) c[i][j][q] = 0.f;

    #define LOAD_TILE(buf, k0)                                                  \
    {                                                                           \
        const float* Ap = A + (size_t)(m0 + lr) * lda + (k0) + lk;              \
        cp16(&As[buf][lr][lk],      Ap, 16);                                    \
        cp16(&As[buf][lr + 64][lk], Ap + (size_t)64 * lda, 16);                 \
        int nr0 = n0 + lr, nr1 = nr0 + 64;                                      \
        int cr0 = nr0 < N ? nr0 : N - 1, cr1 = nr1 < N ? nr1 : N - 1;           \
        cp16(&Bs[buf][lr][lk],      B + (size_t)cr0 * ldb + (k0) + lk,          \
             nr0 < N ? 16 : 0);                                                 \
        cp16(&Bs[buf][lr + 64][lk], B + (size_t)cr1 * ldb + (k0) + lk,          \
             nr1 < N ? 16 : 0);                                                 \
        asm volatile("cp.async.commit_group;");                                 \
    }

    LOAD_TILE(0, 0);
    asm volatile("cp.async.wait_group 0;" ::: "memory");
    __syncthreads();

    const int T = K / 16;
    int p = 0;
    for (int t = 0; t < T; t++) {
        if (t + 1 < T) LOAD_TILE(p ^ 1, (t + 1) * 16);
        #pragma unroll
        for (int kk = 0; kk < 16; kk += 8) {
            unsigned ah[4][4], al[4][4], bh[4][2], bl[4][2];
            #pragma unroll
            for (int mi = 0; mi < 4; mi++) {
                int r = wm + mi * 16 + g;
                spl(As[p][r    ][kk + t4],     ah[mi][0], al[mi][0]);
                spl(As[p][r + 8][kk + t4],     ah[mi][1], al[mi][1]);
                spl(As[p][r    ][kk + t4 + 4], ah[mi][2], al[mi][2]);
                spl(As[p][r + 8][kk + t4 + 4], ah[mi][3], al[mi][3]);
            }
            #pragma unroll
            for (int ni = 0; ni < 4; ni++) {
                int r = wn + ni * 8 + g;
                spl(Bs[p][r][kk + t4],     bh[ni][0], bl[ni][0]);
                spl(Bs[p][r][kk + t4 + 4], bh[ni][1], bl[ni][1]);
            }
            #pragma unroll
            for (int mi = 0; mi < 4; mi++)
                #pragma unroll
                for (int ni = 0; ni < 4; ni++) {
                    float* cc = c[mi][ni];
                    MMA_TF32(cc, ah[mi][0], ah[mi][1], ah[mi][2], ah[mi][3],
                                 bl[ni][0], bl[ni][1]);
                    MMA_TF32(cc, al[mi][0], al[mi][1], al[mi][2], al[mi][3],
                                 bh[ni][0], bh[ni][1]);
                    MMA_TF32(cc, ah[mi][0], ah[mi][1], ah[mi][2], ah[mi][3],
                                 bh[ni][0], bh[ni][1]);
                }
        }
        if (t + 1 < T) {
            asm volatile("cp.async.wait_group 0;" ::: "memory");
            __syncthreads();
            p ^= 1;
        }
    }
    #undef LOAD_TILE

    // ---- normal epilogue ----
    #pragma unroll
    for (int mi = 0; mi < 4; mi++) {
        int r0 = m0 + wm + mi * 16 + g;
        int r1 = r0 + 8;
        float xm0 = 0.f, xm1 = 0.f;
        if (mode == 1) { xm0 = xb[r0]; xm1 = xb[r1]; }
        #pragma unroll
        for (int ni = 0; ni < 4; ni++) {
            int n = n0 + wn + ni * 8 + t4 * 2;
            if (n < N) {
                float v0 = c[mi][ni][0], v1 = c[mi][ni][1];
                float v2 = c[mi][ni][2], v3 = c[mi][ni][3];
                if (mode == 1) {
                    float xn0 = xb[n], xn1 = xb[n + 1];
                    v0 = 2.f * v0 - xm0 - xn0;  v1 = 2.f * v1 - xm0 - xn1;
                    v2 = 2.f * v2 - xm1 - xn0;  v3 = 2.f * v3 - xm1 - xn1;
                } else if (mode == 2) {
                    float s0 = gg[n] * BN_SCALE, s1 = gg[n + 1] * BN_SCALE;
                    float b0v = bb[n], b1v = bb[n + 1];
                    v0 = fmaf(s0, v0, b0v); v0 = (v0 > 0.f) ? v0 : expm1f(v0);
                    v1 = fmaf(s1, v1, b1v); v1 = (v1 > 0.f) ? v1 : expm1f(v1);
                    v2 = fmaf(s0, v2, b0v); v2 = (v2 > 0.f) ? v2 : expm1f(v2);
                    v3 = fmaf(s1, v3, b1v); v3 = (v3 > 0.f) ? v3 : expm1f(v3);
                }
                float2 p0 = {v0, v1}, p1 = {v2, v3};
                *(float2*)&C[(size_t)r0 * ldc + n] = p0;
                *(float2*)&C[(size_t)r1 * ldc + n] = p1;
            }
        }
    }

    // ---- mirror epilogue (sym, strictly lower blocks): C[n][m] via smem transpose ----
    // stride 132 floats = 528B (multiple of 16B) keeps float4 accesses aligned.
    if (sym && blockIdx.x < blockIdx.y) {
        float (*st)[132] = reinterpret_cast<float(*)[132]>(&As[0][0][0]); // 16.9KB < 20KB
        #pragma unroll 1
        for (int s = 0; s < 4; s++) {    // s = ni strip; covers 32 mirror rows
            __syncthreads();
            #pragma unroll
            for (int mi = 0; mi < 4; mi++) {
                int r0l = wm + mi * 16 + g;       // local row 0..127
                int r0 = m0 + r0l, r1 = r0 + 8;
                int n  = n0 + wn + s * 8 + t4 * 2;
                float xm0 = xb[r0], xm1 = xb[r1];
                float xn0 = xb[n],  xn1 = xb[n + 1];
                float v0 = 2.f * c[mi][s][0] - xm0 - xn0;
                float v1 = 2.f * c[mi][s][1] - xm0 - xn1;
                float v2 = 2.f * c[mi][s][2] - xm1 - xn0;
                float v3 = 2.f * c[mi][s][3] - xm1 - xn1;
                int cl = (w >> 1) * 8 + t4 * 2;   // strip-local col 0..31
                st[cl    ][r0l]     = v0;
                st[cl + 1][r0l]     = v1;
                st[cl    ][r0l + 8] = v2;
                st[cl + 1][r0l + 8] = v3;
            }
            __syncthreads();
            int rsel = tid >> 3;                   // 0..31
            int wnq = rsel >> 3, off = rsel & 7;
            int nl = wnq * 32 + s * 8 + off;       // tile-local col = mirror row
            int colm = (tid & 7) * 16;
            float* dst = &C[(size_t)(n0 + nl) * ldc + m0 + colm];
            const float* src = &st[rsel][colm];
            #pragma unroll
            for (int q = 0; q < 4; q++)
                *(float4*)(dst + q * 4) = *(const float4*)(src + q * 4);
        }
    }
}

// ---------------- top-k (k=20): u64 keys, cached top-3 tournament ----------------
// key = ordered(val)<<32 | (1023-idx): larger key = larger val, ties -> lower idx.
__global__ void __launch_bounds__(256) topk_kernel(
        const float* __restrict__ D, int* __restrict__ out) {
    int warp = (blockIdx.x * blockDim.x + threadIdx.x) >> 5;
    int lane = threadIdx.x & 31;
    const float* row = D + (size_t)warp * NP;
    unsigned long long k[32];
    #pragma unroll
    for (int j = 0; j < 32; j++) {
        int idx = lane + j * 32;
        unsigned u = __float_as_uint(row[idx]);
        unsigned o = (u & 0x80000000u) ? ~u : (u | 0x80000000u);
        k[j] = ((unsigned long long)o << 32) | (unsigned)(1023 - idx);
    }
    int base = warp & ~(NP - 1);   // batch base as global row
    unsigned long long s0 = 0, s1 = 0, s2 = 0;
    // initial top-3
    #pragma unroll
    for (int j = 0; j < 32; j++) {
        unsigned long long x = k[j];
        if (x > s0)      { s2 = s1; s1 = s0; s0 = x; }
        else if (x > s1) { s2 = s1; s1 = x; }
        else if (x > s2) { s2 = x; }
    }
    for (int it = 0; it < KNN; it++) {
        unsigned long long wv = s0;
        #pragma unroll
        for (int off = 16; off; off >>= 1) {
            unsigned long long o = __shfl_xor_sync(0xffffffffu, wv, off);
            if (o > wv) wv = o;
        }
        if (s0 == wv) {          // unique winner pops
            s0 = s1; s1 = s2; s2 = 0;
            if (s0 == 0) {       // cache exhausted: refill top-3 among keys < wv
                #pragma unroll
                for (int j = 0; j < 32; j++) {
                    unsigned long long x = k[j];
                    if (x < wv) {
                        if (x > s0)      { s2 = s1; s1 = s0; s0 = x; }
                        else if (x > s1) { s2 = s1; s1 = x; }
                        else if (x > s2) { s2 = x; }
                    }
                }
            }
        }
        if (lane == 0) out[warp * KNN + it] = base + 1023 - (int)(wv & 1023u);
    }
}

// ---------------- edge-conv aggregation (+ fused rowsum for next layer) ----------------
__global__ void __launch_bounds__(256) aggregate_kernel(
        const float* __restrict__ Yn, const float* __restrict__ Yc,
        int C, const int* __restrict__ idx,
        const float* __restrict__ gg, const float* __restrict__ bb,
        float* __restrict__ outp /* = g_cat + off, ld 512 */,
        float* __restrict__ xxout) {
    int r = blockIdx.x;
    int c = threadIdx.x;
    __shared__ int sidx[KNN];
    __shared__ float red[256];
    if (c < KNN) sidx[c] = idx[r * KNN + c];
    __syncthreads();
    float vmax = -INFINITY, vmin = INFINITY;
    #pragma unroll 4
    for (int j = 0; j < KNN; j++) {
        float v = Yn[(size_t)sidx[j] * C + c];
        vmax = fmaxf(vmax, v);
        vmin = fminf(vmin, v);
    }
    float center = Yc[(size_t)r * C + c] - Yn[(size_t)r * C + c];
    float s = gg[c] * BN_SCALE;
    float h = s * ((s >= 0.f ? vmax : vmin) + center) + bb[c];
    float e = (h > 0.f) ? h : expm1f(h);
    outp[(size_t)r * 512 + c] = e;
    if (xxout) {
        red[c] = e * e;
        __syncthreads();
        for (int st = blockDim.x >> 1; st > 0; st >>= 1) {
            if (c < st) red[c] += red[c + st];
            __syncthreads();
        }
        if (c == 0) xxout[r] = red[0];
    }
}

// ---------------- global max/mean pooling ----------------
__global__ void __launch_bounds__(256) pool_partial(
        const float* __restrict__ h,
        float* __restrict__ pmax, float* __restrict__ psum) {
    int o  = blockIdx.y * 256 + threadIdx.x;
    int b  = blockIdx.x;
    int nz = blockIdx.z;
    float m = -INFINITY, s = 0.f;
    for (int n = nz * 64; n < nz * 64 + 64; n++) {
        float v = h[((size_t)(b * NP + n)) * 1024 + o];
        m = fmaxf(m, v); s += v;
    }
    pmax[(nz * NB + b) * 1024 + o] = m;
    psum[(nz * NB + b) * 1024 + o] = s;
}

__global__ void __launch_bounds__(256) pool_combine(
        const float* __restrict__ pmax, const float* __restrict__ psum,
        float* __restrict__ f) {
    int t = blockIdx.x * 256 + threadIdx.x;
    if (t >= NB * 1024) return;
    int b = t >> 10, o = t & 1023;
    float m = -INFINITY, s = 0.f;
    for (int c = 0; c < 16; c++) {
        m = fmaxf(m, pmax[(c * NB + b) * 1024 + o]);
        s += psum[(c * NB + b) * 1024 + o];
    }
    f[b * 2048 + o] = m;
    f[b * 2048 + 1024 + o] = s * (1.f / 1024.f);
}

// ---------------- tiny MLP: one warp per output element ----------------
__global__ void __launch_bounds__(256) mlp_kernel(
        const float* __restrict__ in, int Kd,
        const float* __restrict__ W,
        const float* __restrict__ gg, const float* __restrict__ bb,
        float* __restrict__ out, int Nout, int rows, int bnelu) {
    int wid  = (blockIdx.x * blockDim.x + threadIdx.x) >> 5;
    int lane = threadIdx.x & 31;
    if (wid >= rows * Nout) return;
    int r = wid / Nout, o = wid % Nout;
    const float* a = in + (size_t)r * Kd;
    const float* w = W  + (size_t)o * Kd;
    float s = 0.f;
    for (int k = lane; k < Kd; k += 32) s += a[k] * w[k];
    #pragma unroll
    for (int off = 16; off; off >>= 1) s += __shfl_xor_sync(0xffffffffu, s, off);
    if (lane == 0) {
        float v;
        if (bnelu) {
            float sc = gg[o] * BN_SCALE;
            v = fmaf(sc, s, bb[o]);
            v = (v > 0.f) ? v : expm1f(v);
        } else {
            v = s + bb[o];
        }
        out[(size_t)r * Nout + o] = v;
    }
}

extern "C" void kernel_launch(void* const* d_in, const int* in_sizes, int n_in,
                              void* d_out, int out_size) {
    const float* x   = (const float*)d_in[0];
    const float* W1  = (const float*)d_in[1];
    const float* g1  = (const float*)d_in[2];
    const float* b1  = (const float*)d_in[3];
    const float* W2  = (const float*)d_in[4];
    const float* g2  = (const float*)d_in[5];
    const float* b2  = (const float*)d_in[6];
    const float* W3  = (const float*)d_in[7];
    const float* g3  = (const float*)d_in[8];
    const float* b3  = (const float*)d_in[9];
    const float* W4  = (const float*)d_in[10];
    const float* g4  = (const float*)d_in[11];
    const float* b4  = (const float*)d_in[12];
    const float* W5  = (const float*)d_in[13];
    const float* g5  = (const float*)d_in[14];
    const float* b5  = (const float*)d_in[15];
    const float* Wl1 = (const float*)d_in[16];
    const float* gl1 = (const float*)d_in[17];
    const float* bl1 = (const float*)d_in[18];
    const float* Wl2 = (const float*)d_in[19];
    const float* gl2 = (const float*)d_in[20];
    const float* bl2 = (const float*)d_in[21];
    const float* Wl3 = (const float*)d_in[22];
    const float* bl3 = (const float*)d_in[23];

    float *dist, *cat, *Y, *xx, *pmax, *psum, *f, *f1, *f2;
    int* idx;
    cudaGetSymbolAddress((void**)&dist, g_dist);
    cudaGetSymbolAddress((void**)&cat,  g_cat);
    cudaGetSymbolAddress((void**)&Y,    g_Y);
    cudaGetSymbolAddress((void**)&xx,   g_xx);
    cudaGetSymbolAddress((void**)&idx,  g_idx);
    cudaGetSymbolAddress((void**)&pmax, g_pmax);
    cudaGetSymbolAddress((void**)&psum, g_psum);
    cudaGetSymbolAddress((void**)&f,    g_f);
    cudaGetSymbolAddress((void**)&f1,   g_f1);
    cudaGetSymbolAddress((void**)&f2,   g_f2);

    dim3 blk(16, 16);

    // ---------- layer 1 (fp32, K=3) ----------
    rowsum_kernel<<<NR / 256, 256>>>(x, 3, 3, xx);
    gemm_nt<<<dim3(NP / 64, NP / 64, NB), blk>>>(1, x, 3, NP * 3, x, 3, NP * 3,
                                                 dist, NP, NP * NP, 3, xx, NP);
    topk_kernel<<<NR / 8, 256>>>(dist, idx);
    // merged Yn/Yc: z=0 -> Wd, z=1 -> Wc
    gemm_nt<<<dim3(1, NR / 64, 2), blk>>>(0, x, 3, 0, W1, 6, 3,
                                          Y, 64, NR * 64, 3, nullptr, 0);
    aggregate_kernel<<<NR, 64>>>(Y, Y + (size_t)NR * 64, 64, idx, g1, b1, cat + 0, xx);

    // ---------- layers 2-4 (split-tf32) ----------
    struct { const float* X; int Cin; const float* W; const float* g; const float* b;
             int Cout; int off; } L[3] = {
        { cat + 0,   64,  W2, g2, b2,  64,  64 },
        { cat + 64,  64,  W3, g3, b3, 128, 128 },
        { cat + 128, 128, W4, g4, b4, 256, 256 },
    };
    for (int li = 0; li < 3; li++) {
        // symmetric dist (xx from previous aggregate)
        gemm_tf32<<<dim3(NP / 128, NP / 128, NB), 256>>>(1, NP, 1,
            L[li].X, 512, NP * 512, L[li].X, 512, NP * 512,
            dist, NP, NP * NP, L[li].Cin, xx, NP, nullptr, nullptr);
        topk_kernel<<<NR / 8, 256>>>(dist, idx);
        // merged Yn/Yc via z
        gemm_tf32<<<dim3((L[li].Cout + 127) / 128, NR / 128, 2), 256>>>(0, L[li].Cout, 0,
            L[li].X, 512, 0, L[li].W, 2 * L[li].Cin, L[li].Cin,
            Y, L[li].Cout, NR * L[li].Cout, L[li].Cin, nullptr, 0, nullptr, nullptr);
        aggregate_kernel<<<NR, L[li].Cout>>>(Y, Y + (size_t)NR * L[li].Cout,
            L[li].Cout, idx, L[li].g, L[li].b, cat + L[li].off,
            (li < 2) ? xx : nullptr);
    }

    // ---------- conv5: h = elu(bn(cat @ W5^T)), reuse dist as h ----------
    gemm_tf32<<<dim3(1024 / 128, NR / 128, 1), 256>>>(2, 1024, 0,
        cat, 512, 0, W5, 512, 0,
        dist, 1024, 0, 512, nullptr, 0, g5, b5);

    // ---------- pooling + MLP head ----------
    pool_partial<<<dim3(NB, 4, 16), 256>>>(dist, pmax, psum);
    pool_combine<<<32, 256>>>(pmax, psum, f);
    mlp_kernel<<<512, 256>>>(f,  2048, Wl1, gl1, bl1, f1, 512, NB, 1);
    mlp_kernel<<<256, 256>>>(f1, 512,  Wl2, gl2, bl2, f2, 256, NB, 1);
    mlp_kernel<<<40,  256>>>(f2, 256,  Wl3, nullptr, bl3, (float*)d_out, 40, NB, 0);
}

// round 9
// speedup vs baseline: 1.5233x; 1.4500x over previous
#include <cuda_runtime.h>
#include <math.h>

#define BN_SCALE 0.99999500003749972f

#define NB 8
#define NP 1024
#define NR (NB*NP)     // 8192 rows total
#define KNN 20

// ---------------- static scratch (no allocations allowed) ----------------
__device__ __align__(16) float g_dist[(size_t)NR * NP];   // 32MB (dist only now)
__device__ __align__(16) float g_cat [(size_t)NR * 512];  // x1|x2|x3|x4 concatenated
__device__ __align__(16) float g_Y   [(size_t)2 * NR * 256];  // Yn | Yc (z-batched)
__device__ float g_xx[NR];
__device__ int   g_idx[NR * KNN];
__device__ float g_pmax[64 * 1024];
__device__ float g_psum[64 * 1024];
__device__ float g_f [NB * 2048];
__device__ float g_f1[NB * 512];
__device__ float g_f2[NB * 256];

// ---------------- row sum of squares (layer 1 only) ----------------
__global__ void __launch_bounds__(256) rowsum_kernel(
        const float* __restrict__ X, int ld, int C, float* __restrict__ xx) {
    int r = blockIdx.x * blockDim.x + threadIdx.x;
    if (r >= NR) return;
    const float* p = X + (size_t)r * ld;
    float s = 0.f;
    for (int c = 0; c < C; c++) s += p[c] * p[c];
    xx[r] = s;
}

// ---------------- fp32 NT GEMM (layer-1 K=3 only) ----------------
__global__ void __launch_bounds__(256) gemm_nt(int mode,
                        const float* __restrict__ A, int lda, int batA,
                        const float* __restrict__ B, int ldb, int batB,
                        float* __restrict__ C, int ldc, int batC, int K,
                        const float* __restrict__ xx, int batX)
{
    A += (size_t)blockIdx.z * batA;
    B += (size_t)blockIdx.z * batB;
    C += (size_t)blockIdx.z * batC;
    const int m0 = blockIdx.y * 64;
    const int n0 = blockIdx.x * 64;
    __shared__ __align__(16) float As[16][64];
    __shared__ __align__(16) float Bs[16][64];
    const int tx = threadIdx.x, ty = threadIdx.y;
    const int t = ty * 16 + tx;
    const int lm = t >> 2;
    const int lk = (t & 3) * 4;
    float acc[4][4] = {};
    for (int k0 = 0; k0 < K; k0 += 16) {
        #pragma unroll
        for (int u = 0; u < 4; u++) {
            int kk = lk + u;
            As[kk][lm] = (k0 + kk < K) ? A[(size_t)(m0 + lm) * lda + k0 + kk] : 0.f;
            Bs[kk][lm] = (k0 + kk < K) ? B[(size_t)(n0 + lm) * ldb + k0 + kk] : 0.f;
        }
        __syncthreads();
        #pragma unroll
        for (int kk = 0; kk < 16; kk++) {
            float4 a4 = *reinterpret_cast<const float4*>(&As[kk][ty * 4]);
            float4 b4 = *reinterpret_cast<const float4*>(&Bs[kk][tx * 4]);
            float a[4] = {a4.x, a4.y, a4.z, a4.w};
            float b[4] = {b4.x, b4.y, b4.z, b4.w};
            #pragma unroll
            for (int i = 0; i < 4; i++)
                #pragma unroll
                for (int j = 0; j < 4; j++)
                    acc[i][j] = fmaf(a[i], b[j], acc[i][j]);
        }
        __syncthreads();
    }
    #pragma unroll
    for (int i = 0; i < 4; i++) {
        int m = m0 + ty * 4 + i;
        int n = n0 + tx * 4;
        float4 v; float* vp = &v.x;
        if (mode == 1) {
            float xm = xx[batX * blockIdx.z + m];
            #pragma unroll
            for (int j = 0; j < 4; j++)
                vp[j] = 2.f * acc[i][j] - xm - xx[batX * blockIdx.z + n + j];
        } else {
            #pragma unroll
            for (int j = 0; j < 4; j++) vp[j] = acc[i][j];
        }
        *reinterpret_cast<float4*>(&C[(size_t)m * ldc + n]) = v;
    }
}

// ---------------- tf32 tensor-core NT GEMM ----------------
// NSPLIT=3: 3xTF32 compensated (~fp32). NSPLIT=1: plain tf32 (cvt.rna).
// Block 128x128, 8 warps 2(m)x4(n), warp tile 64x32, mma m16n8k8.
// fp32 tiles in smem (double-buffered, cp.async); split/cvt at frag load.
// mode 1 + sym: lower triangle + mirror. mode 3: fused BN/ELU + max/sum pooling
// over the block's 128 rows (no C store; writes per-block partials).
__device__ __forceinline__ unsigned f2tf(float f) {
    unsigned u; asm("cvt.rna.tf32.f32 %0, %1;" : "=r"(u) : "f"(f)); return u;
}
__device__ __forceinline__ void spl(float f, unsigned& hi, unsigned& lo) {
    hi = f2tf(f);
    lo = f2tf(f - __uint_as_float(hi));
}
__device__ __forceinline__ void cp16(void* dst, const void* src, int sz) {
    unsigned d = (unsigned)__cvta_generic_to_shared(dst);
    asm volatile("cp.async.ca.shared.global [%0], [%1], 16, %2;"
                 :: "r"(d), "l"(src), "r"(sz));
}
#define MMA_TF32(c, a0,a1,a2,a3, b0,b1)                                        \
    asm volatile("mma.sync.aligned.m16n8k8.row.col.f32.tf32.tf32.f32 "          \
                 "{%0,%1,%2,%3}, {%4,%5,%6,%7}, {%8,%9}, {%0,%1,%2,%3};"        \
                 : "+f"(c[0]), "+f"(c[1]), "+f"(c[2]), "+f"(c[3])               \
                 : "r"(a0), "r"(a1), "r"(a2), "r"(a3), "r"(b0), "r"(b1))

template<int NSPLIT>
__global__ void __launch_bounds__(256) gemm_tf32_t(int mode, int N, int sym,
        const float* __restrict__ A, int lda, int batA,
        const float* __restrict__ B, int ldb, int batB,
        float* __restrict__ C, int ldc, int batC, int K,
        const float* __restrict__ xx, int batX,
        const float* __restrict__ gg, const float* __restrict__ bb,
        float* __restrict__ pomax, float* __restrict__ posum)
{
    if (sym && blockIdx.x > blockIdx.y) return;   // lower triangle only
    A += (size_t)blockIdx.z * batA;
    B += (size_t)blockIdx.z * batB;
    C += (size_t)blockIdx.z * batC;
    const float* xb = xx ? (xx + (size_t)batX * blockIdx.z) : xx;

    const int m0 = blockIdx.y * 128;
    const int n0 = blockIdx.x * 128;

    __shared__ __align__(16) float As[2][128][20];   // fp32 tiles, 20KB
    __shared__ __align__(16) float Bs[2][128][20];   // 20KB

    const int tid = threadIdx.x;
    const int w  = tid >> 5, l = tid & 31;
    const int g  = l >> 2,  t4 = l & 3;
    const int wm = (w & 1) * 64;
    const int wn = (w >> 1) * 32;
    const int lr = tid >> 2;          // 0..63
    const int lk = (tid & 3) * 4;     // 0,4,8,12

    float c[4][4][4];
    #pragma unroll
    for (int i = 0; i < 4; i++)
        #pragma unroll
        for (int j = 0; j < 4; j++)
            #pragma unroll
            for (int q = 0; q < 4; q++) c[i][j][q] = 0.f;

    #define LOAD_TILE(buf, k0)                                                  \
    {                                                                           \
        const float* Ap = A + (size_t)(m0 + lr) * lda + (k0) + lk;              \
        cp16(&As[buf][lr][lk],      Ap, 16);                                    \
        cp16(&As[buf][lr + 64][lk], Ap + (size_t)64 * lda, 16);                 \
        int nr0 = n0 + lr, nr1 = nr0 + 64;                                      \
        int cr0 = nr0 < N ? nr0 : N - 1, cr1 = nr1 < N ? nr1 : N - 1;           \
        cp16(&Bs[buf][lr][lk],      B + (size_t)cr0 * ldb + (k0) + lk,          \
             nr0 < N ? 16 : 0);                                                 \
        cp16(&Bs[buf][lr + 64][lk], B + (size_t)cr1 * ldb + (k0) + lk,          \
             nr1 < N ? 16 : 0);                                                 \
        asm volatile("cp.async.commit_group;");                                 \
    }

    LOAD_TILE(0, 0);
    asm volatile("cp.async.wait_group 0;" ::: "memory");
    __syncthreads();

    const int T = K / 16;
    int p = 0;
    for (int t = 0; t < T; t++) {
        if (t + 1 < T) LOAD_TILE(p ^ 1, (t + 1) * 16);
        #pragma unroll
        for (int kk = 0; kk < 16; kk += 8) {
            unsigned ah[4][4], bh[4][2];
            unsigned al[4][4], bl[4][2];
            #pragma unroll
            for (int mi = 0; mi < 4; mi++) {
                int r = wm + mi * 16 + g;
                if (NSPLIT == 3) {
                    spl(As[p][r    ][kk + t4],     ah[mi][0], al[mi][0]);
                    spl(As[p][r + 8][kk + t4],     ah[mi][1], al[mi][1]);
                    spl(As[p][r    ][kk + t4 + 4], ah[mi][2], al[mi][2]);
                    spl(As[p][r + 8][kk + t4 + 4], ah[mi][3], al[mi][3]);
                } else {
                    ah[mi][0] = f2tf(As[p][r    ][kk + t4]);
                    ah[mi][1] = f2tf(As[p][r + 8][kk + t4]);
                    ah[mi][2] = f2tf(As[p][r    ][kk + t4 + 4]);
                    ah[mi][3] = f2tf(As[p][r + 8][kk + t4 + 4]);
                }
            }
            #pragma unroll
            for (int ni = 0; ni < 4; ni++) {
                int r = wn + ni * 8 + g;
                if (NSPLIT == 3) {
                    spl(Bs[p][r][kk + t4],     bh[ni][0], bl[ni][0]);
                    spl(Bs[p][r][kk + t4 + 4], bh[ni][1], bl[ni][1]);
                } else {
                    bh[ni][0] = f2tf(Bs[p][r][kk + t4]);
                    bh[ni][1] = f2tf(Bs[p][r][kk + t4 + 4]);
                }
            }
            #pragma unroll
            for (int mi = 0; mi < 4; mi++)
                #pragma unroll
                for (int ni = 0; ni < 4; ni++) {
                    float* cc = c[mi][ni];
                    if (NSPLIT == 3) {
                        MMA_TF32(cc, ah[mi][0], ah[mi][1], ah[mi][2], ah[mi][3],
                                     bl[ni][0], bl[ni][1]);
                        MMA_TF32(cc, al[mi][0], al[mi][1], al[mi][2], al[mi][3],
                                     bh[ni][0], bh[ni][1]);
                    }
                    MMA_TF32(cc, ah[mi][0], ah[mi][1], ah[mi][2], ah[mi][3],
                                 bh[ni][0], bh[ni][1]);
                }
        }
        if (t + 1 < T) {
            asm volatile("cp.async.wait_group 0;" ::: "memory");
            __syncthreads();
            p ^= 1;
        }
    }
    #undef LOAD_TILE

    // ---- mode 3: fused BN/ELU + max/sum pooling over this block's 128 rows ----
    if (mode == 3) {
        __syncthreads();                               // mma done reading As
        float* pm = &As[0][0][0];                      // [2][128]
        float* ps = pm + 256;
        #pragma unroll
        for (int ni = 0; ni < 4; ni++) {
            #pragma unroll
            for (int j = 0; j < 2; j++) {
                int cl = wn + ni * 8 + t4 * 2 + j;     // 0..127 column in tile
                int n  = n0 + cl;
                float sc = gg[n] * BN_SCALE, bv = bb[n];
                float vmax = -INFINITY, vsum = 0.f;
                #pragma unroll
                for (int mi = 0; mi < 4; mi++) {
                    float va = fmaf(sc, c[mi][ni][j],     bv);
                    va = (va > 0.f) ? va : expm1f(va);
                    float vb = fmaf(sc, c[mi][ni][j + 2], bv);
                    vb = (vb > 0.f) ? vb : expm1f(vb);
                    vmax = fmaxf(vmax, fmaxf(va, vb));
                    vsum += va + vb;
                }
                #pragma unroll
                for (int off = 4; off <= 16; off <<= 1) {
                    vmax = fmaxf(vmax, __shfl_xor_sync(0xffffffffu, vmax, off));
                    vsum += __shfl_xor_sync(0xffffffffu, vsum, off);
                }
                if (g == 0) {
                    pm[(w & 1) * 128 + cl] = vmax;
                    ps[(w & 1) * 128 + cl] = vsum;
                }
            }
        }
        __syncthreads();
        if (tid < 128) {
            int o = blockIdx.y * 1024 + n0 + tid;
            pomax[o] = fmaxf(pm[tid], pm[128 + tid]);
            posum[o] = ps[tid] + ps[128 + tid];
        }
        return;
    }

    // ---- normal epilogue ----
    #pragma unroll
    for (int mi = 0; mi < 4; mi++) {
        int r0 = m0 + wm + mi * 16 + g;
        int r1 = r0 + 8;
        float xm0 = 0.f, xm1 = 0.f;
        if (mode == 1) { xm0 = xb[r0]; xm1 = xb[r1]; }
        #pragma unroll
        for (int ni = 0; ni < 4; ni++) {
            int n = n0 + wn + ni * 8 + t4 * 2;
            if (n < N) {
                float v0 = c[mi][ni][0], v1 = c[mi][ni][1];
                float v2 = c[mi][ni][2], v3 = c[mi][ni][3];
                if (mode == 1) {
                    float xn0 = xb[n], xn1 = xb[n + 1];
                    v0 = 2.f * v0 - xm0 - xn0;  v1 = 2.f * v1 - xm0 - xn1;
                    v2 = 2.f * v2 - xm1 - xn0;  v3 = 2.f * v3 - xm1 - xn1;
                }
                float2 p0 = {v0, v1}, p1 = {v2, v3};
                *(float2*)&C[(size_t)r0 * ldc + n] = p0;
                *(float2*)&C[(size_t)r1 * ldc + n] = p1;
            }
        }
    }

    // ---- mirror epilogue (sym, strictly lower blocks) ----
    if (sym && blockIdx.x < blockIdx.y) {
        float (*st)[132] = reinterpret_cast<float(*)[132]>(&As[0][0][0]); // aligned stride
        #pragma unroll 1
        for (int s = 0; s < 4; s++) {
            __syncthreads();
            #pragma unroll
            for (int mi = 0; mi < 4; mi++) {
                int r0l = wm + mi * 16 + g;
                int r0 = m0 + r0l, r1 = r0 + 8;
                int n  = n0 + wn + s * 8 + t4 * 2;
                float xm0 = xb[r0], xm1 = xb[r1];
                float xn0 = xb[n],  xn1 = xb[n + 1];
                float v0 = 2.f * c[mi][s][0] - xm0 - xn0;
                float v1 = 2.f * c[mi][s][1] - xm0 - xn1;
                float v2 = 2.f * c[mi][s][2] - xm1 - xn0;
                float v3 = 2.f * c[mi][s][3] - xm1 - xn1;
                int cl = (w >> 1) * 8 + t4 * 2;
                st[cl    ][r0l]     = v0;
                st[cl + 1][r0l]     = v1;
                st[cl    ][r0l + 8] = v2;
                st[cl + 1][r0l + 8] = v3;
            }
            __syncthreads();
            int rsel = tid >> 3;
            int wnq = rsel >> 3, off = rsel & 7;
            int nl = wnq * 32 + s * 8 + off;
            int colm = (tid & 7) * 16;
            float* dst = &C[(size_t)(n0 + nl) * ldc + m0 + colm];
            const float* src = &st[rsel][colm];
            #pragma unroll
            for (int q = 0; q < 4; q++)
                *(float4*)(dst + q * 4) = *(const float4*)(src + q * 4);
        }
    }
}

// ---------------- top-k (k=20): u64 keys, cached top-3 tournament ----------------
__global__ void __launch_bounds__(256) topk_kernel(
        const float* __restrict__ D, int* __restrict__ out) {
    int warp = (blockIdx.x * blockDim.x + threadIdx.x) >> 5;
    int lane = threadIdx.x & 31;
    const float* row = D + (size_t)warp * NP;
    unsigned long long k[32];
    #pragma unroll
    for (int j = 0; j < 32; j++) {
        int idx = lane + j * 32;
        unsigned u = __float_as_uint(row[idx]);
        unsigned o = (u & 0x80000000u) ? ~u : (u | 0x80000000u);
        k[j] = ((unsigned long long)o << 32) | (unsigned)(1023 - idx);
    }
    int base = warp & ~(NP - 1);
    unsigned long long s0 = 0, s1 = 0, s2 = 0;
    #pragma unroll
    for (int j = 0; j < 32; j++) {
        unsigned long long x = k[j];
        if (x > s0)      { s2 = s1; s1 = s0; s0 = x; }
        else if (x > s1) { s2 = s1; s1 = x; }
        else if (x > s2) { s2 = x; }
    }
    for (int it = 0; it < KNN; it++) {
        unsigned long long wv = s0;
        #pragma unroll
        for (int off = 16; off; off >>= 1) {
            unsigned long long o = __shfl_xor_sync(0xffffffffu, wv, off);
            if (o > wv) wv = o;
        }
        if (s0 == wv) {
            s0 = s1; s1 = s2; s2 = 0;
            if (s0 == 0) {
                #pragma unroll
                for (int j = 0; j < 32; j++) {
                    unsigned long long x = k[j];
                    if (x < wv) {
                        if (x > s0)      { s2 = s1; s1 = s0; s0 = x; }
                        else if (x > s1) { s2 = s1; s1 = x; }
                        else if (x > s2) { s2 = x; }
                    }
                }
            }
        }
        if (lane == 0) out[warp * KNN + it] = base + 1023 - (int)(wv & 1023u);
    }
}

// ---------------- edge-conv aggregation (+ fused rowsum for next layer) ----------------
__global__ void __launch_bounds__(256) aggregate_kernel(
        const float* __restrict__ Yn, const float* __restrict__ Yc,
        int C, const int* __restrict__ idx,
        const float* __restrict__ gg, const float* __restrict__ bb,
        float* __restrict__ outp, float* __restrict__ xxout) {
    int r = blockIdx.x;
    int c = threadIdx.x;
    __shared__ int sidx[KNN];
    __shared__ float red[256];
    if (c < KNN) sidx[c] = idx[r * KNN + c];
    __syncthreads();
    float vmax = -INFINITY, vmin = INFINITY;
    #pragma unroll 4
    for (int j = 0; j < KNN; j++) {
        float v = Yn[(size_t)sidx[j] * C + c];
        vmax = fmaxf(vmax, v);
        vmin = fminf(vmin, v);
    }
    float center = Yc[(size_t)r * C + c] - Yn[(size_t)r * C + c];
    float s = gg[c] * BN_SCALE;
    float h = s * ((s >= 0.f ? vmax : vmin) + center) + bb[c];
    float e = (h > 0.f) ? h : expm1f(h);
    outp[(size_t)r * 512 + c] = e;
    if (xxout) {
        red[c] = e * e;
        __syncthreads();
        for (int st = blockDim.x >> 1; st > 0; st >>= 1) {
            if (c < st) red[c] += red[c + st];
            __syncthreads();
        }
        if (c == 0) xxout[r] = red[0];
    }
}

// ---------------- pooling combine (8 partial m-blocks per batch) ----------------
__global__ void __launch_bounds__(256) pool_combine(
        const float* __restrict__ pmax, const float* __restrict__ psum,
        float* __restrict__ f) {
    int t = blockIdx.x * 256 + threadIdx.x;
    if (t >= NB * 1024) return;
    int b = t >> 10, o = t & 1023;
    float m = -INFINITY, s = 0.f;
    for (int c = 0; c < 8; c++) {
        m = fmaxf(m, pmax[(b * 8 + c) * 1024 + o]);
        s += psum[(b * 8 + c) * 1024 + o];
    }
    f[b * 2048 + o] = m;
    f[b * 2048 + 1024 + o] = s * (1.f / 1024.f);
}

// ---------------- tiny MLP: one warp per output element ----------------
__global__ void __launch_bounds__(256) mlp_kernel(
        const float* __restrict__ in, int Kd,
        const float* __restrict__ W,
        const float* __restrict__ gg, const float* __restrict__ bb,
        float* __restrict__ out, int Nout, int rows, int bnelu) {
    int wid  = (blockIdx.x * blockDim.x + threadIdx.x) >> 5;
    int lane = threadIdx.x & 31;
    if (wid >= rows * Nout) return;
    int r = wid / Nout, o = wid % Nout;
    const float* a = in + (size_t)r * Kd;
    const float* w = W  + (size_t)o * Kd;
    float s = 0.f;
    for (int k = lane; k < Kd; k += 32) s += a[k] * w[k];
    #pragma unroll
    for (int off = 16; off; off >>= 1) s += __shfl_xor_sync(0xffffffffu, s, off);
    if (lane == 0) {
        float v;
        if (bnelu) {
            float sc = gg[o] * BN_SCALE;
            v = fmaf(sc, s, bb[o]);
            v = (v > 0.f) ? v : expm1f(v);
        } else {
            v = s + bb[o];
        }
        out[(size_t)r * Nout + o] = v;
    }
}

extern "C" void kernel_launch(void* const* d_in, const int* in_sizes, int n_in,
                              void* d_out, int out_size) {
    const float* x   = (const float*)d_in[0];
    const float* W1  = (const float*)d_in[1];
    const float* g1  = (const float*)d_in[2];
    const float* b1  = (const float*)d_in[3];
    const float* W2  = (const float*)d_in[4];
    const float* g2  = (const float*)d_in[5];
    const float* b2  = (const float*)d_in[6];
    const float* W3  = (const float*)d_in[7];
    const float* g3  = (const float*)d_in[8];
    const float* b3  = (const float*)d_in[9];
    const float* W4  = (const float*)d_in[10];
    const float* g4  = (const float*)d_in[11];
    const float* b4  = (const float*)d_in[12];
    const float* W5  = (const float*)d_in[13];
    const float* g5  = (const float*)d_in[14];
    const float* b5  = (const float*)d_in[15];
    const float* Wl1 = (const float*)d_in[16];
    const float* gl1 = (const float*)d_in[17];
    const float* bl1 = (const float*)d_in[18];
    const float* Wl2 = (const float*)d_in[19];
    const float* gl2 = (const float*)d_in[20];
    const float* bl2 = (const float*)d_in[21];
    const float* Wl3 = (const float*)d_in[22];
    const float* bl3 = (const float*)d_in[23];

    float *dist, *cat, *Y, *xx, *pmax, *psum, *f, *f1, *f2;
    int* idx;
    cudaGetSymbolAddress((void**)&dist, g_dist);
    cudaGetSymbolAddress((void**)&cat,  g_cat);
    cudaGetSymbolAddress((void**)&Y,    g_Y);
    cudaGetSymbolAddress((void**)&xx,   g_xx);
    cudaGetSymbolAddress((void**)&idx,  g_idx);
    cudaGetSymbolAddress((void**)&pmax, g_pmax);
    cudaGetSymbolAddress((void**)&psum, g_psum);
    cudaGetSymbolAddress((void**)&f,    g_f);
    cudaGetSymbolAddress((void**)&f1,   g_f1);
    cudaGetSymbolAddress((void**)&f2,   g_f2);

    dim3 blk(16, 16);

    // ---------- layer 1 (fp32, K=3) ----------
    rowsum_kernel<<<NR / 256, 256>>>(x, 3, 3, xx);
    gemm_nt<<<dim3(NP / 64, NP / 64, NB), blk>>>(1, x, 3, NP * 3, x, 3, NP * 3,
                                                 dist, NP, NP * NP, 3, xx, NP);
    topk_kernel<<<NR / 8, 256>>>(dist, idx);
    gemm_nt<<<dim3(1, NR / 64, 2), blk>>>(0, x, 3, 0, W1, 6, 3,
                                          Y, 64, NR * 64, 3, nullptr, 0);
    aggregate_kernel<<<NR, 64>>>(Y, Y + (size_t)NR * 64, 64, idx, g1, b1, cat + 0, xx);

    // ---------- layers 2-4 (split-tf32, 3-mma compensated) ----------
    struct { const float* X; int Cin; const float* W; const float* g; const float* b;
             int Cout; int off; } L[3] = {
        { cat + 0,   64,  W2, g2, b2,  64,  64 },
        { cat + 64,  64,  W3, g3, b3, 128, 128 },
        { cat + 128, 128, W4, g4, b4, 256, 256 },
    };
    for (int li = 0; li < 3; li++) {
        gemm_tf32_t<3><<<dim3(NP / 128, NP / 128, NB), 256>>>(1, NP, 1,
            L[li].X, 512, NP * 512, L[li].X, 512, NP * 512,
            dist, NP, NP * NP, L[li].Cin, xx, NP, nullptr, nullptr,
            nullptr, nullptr);
        topk_kernel<<<NR / 8, 256>>>(dist, idx);
        gemm_tf32_t<3><<<dim3((L[li].Cout + 127) / 128, NR / 128, 2), 256>>>(0, L[li].Cout, 0,
            L[li].X, 512, 0, L[li].W, 2 * L[li].Cin, L[li].Cin,
            Y, L[li].Cout, NR * L[li].Cout, L[li].Cin, nullptr, 0, nullptr, nullptr,
            nullptr, nullptr);
        aggregate_kernel<<<NR, L[li].Cout>>>(Y, Y + (size_t)NR * L[li].Cout,
            L[li].Cout, idx, L[li].g, L[li].b, cat + L[li].off,
            (li < 2) ? xx : nullptr);
    }

    // ---------- conv5: plain tf32, fused BN/ELU + pooling partials ----------
    gemm_tf32_t<1><<<dim3(1024 / 128, NR / 128, 1), 256>>>(3, 1024, 0,
        cat, 512, 0, W5, 512, 0,
        nullptr, 0, 0, 512, nullptr, 0, g5, b5,
        pmax, psum);

    // ---------- pooling combine + MLP head ----------
    pool_combine<<<32, 256>>>(pmax, psum, f);
    mlp_kernel<<<512, 256>>>(f,  2048, Wl1, gl1, bl1, f1, 512, NB, 1);
    mlp_kernel<<<256, 256>>>(f1, 512,  Wl2, gl2, bl2, f2, 256, NB, 1);
    mlp_kernel<<<40,  256>>>(f2, 256,  Wl3, nullptr, bl3, (float*)d_out, 40, NB, 0);
}

// round 12
// speedup vs baseline: 1.7662x; 1.1595x over previous
#include <cuda_runtime.h>
#include <stdint.h>
#include <math.h>

#define BN_SCALE 0.99999500003749972f

#define NB 8
#define NP 1024
#define NR (NB*NP)     // 8192 rows total
#define KNN 20

// ---------------- static scratch (no allocations allowed) ----------------
__device__ __align__(16) float g_dist[(size_t)NR * NP];   // 32MB (dist only)
__device__ __align__(16) float g_cat [(size_t)NR * 512];  // x1|x2|x3|x4 concatenated
__device__ __align__(16) float g_Y   [(size_t)2 * NR * 256];  // Yn | Yc (z-batched)
__device__ float g_xx[NR];
__device__ int   g_idx[NR * KNN];
__device__ float g_pmax[64 * 1024];
__device__ float g_psum[64 * 1024];
__device__ float g_f [NB * 2048];
__device__ float g_f1[NB * 512];
__device__ float g_f2[NB * 256];

// ---------------- row sum of squares (layer 1 only) ----------------
__global__ void __launch_bounds__(256) rowsum_kernel(
        const float* __restrict__ X, int ld, int C, float* __restrict__ xx) {
    int r = blockIdx.x * blockDim.x + threadIdx.x;
    if (r >= NR) return;
    const float* p = X + (size_t)r * ld;
    float s = 0.f;
    for (int c = 0; c < C; c++) s += p[c] * p[c];
    xx[r] = s;
}

// ---------------- fp32 NT GEMM (layer-1 K=3 only) ----------------
__global__ void __launch_bounds__(256) gemm_nt(int mode,
                        const float* __restrict__ A, int lda, int batA,
                        const float* __restrict__ B, int ldb, int batB,
                        float* __restrict__ C, int ldc, int batC, int K,
                        const float* __restrict__ xx, int batX)
{
    A += (size_t)blockIdx.z * batA;
    B += (size_t)blockIdx.z * batB;
    C += (size_t)blockIdx.z * batC;
    const int m0 = blockIdx.y * 64;
    const int n0 = blockIdx.x * 64;
    __shared__ __align__(16) float As[16][64];
    __shared__ __align__(16) float Bs[16][64];
    const int tx = threadIdx.x, ty = threadIdx.y;
    const int t = ty * 16 + tx;
    const int lm = t >> 2;
    const int lk = (t & 3) * 4;
    float acc[4][4] = {};
    for (int k0 = 0; k0 < K; k0 += 16) {
        #pragma unroll
        for (int u = 0; u < 4; u++) {
            int kk = lk + u;
            As[kk][lm] = (k0 + kk < K) ? A[(size_t)(m0 + lm) * lda + k0 + kk] : 0.f;
            Bs[kk][lm] = (k0 + kk < K) ? B[(size_t)(n0 + lm) * ldb + k0 + kk] : 0.f;
        }
        __syncthreads();
        #pragma unroll
        for (int kk = 0; kk < 16; kk++) {
            float4 a4 = *reinterpret_cast<const float4*>(&As[kk][ty * 4]);
            float4 b4 = *reinterpret_cast<const float4*>(&Bs[kk][tx * 4]);
            float a[4] = {a4.x, a4.y, a4.z, a4.w};
            float b[4] = {b4.x, b4.y, b4.z, b4.w};
            #pragma unroll
            for (int i = 0; i < 4; i++)
                #pragma unroll
                for (int j = 0; j < 4; j++)
                    acc[i][j] = fmaf(a[i], b[j], acc[i][j]);
        }
        __syncthreads();
    }
    #pragma unroll
    for (int i = 0; i < 4; i++) {
        int m = m0 + ty * 4 + i;
        int n = n0 + tx * 4;
        float4 v; float* vp = &v.x;
        if (mode == 1) {
            float xm = xx[batX * blockIdx.z + m];
            #pragma unroll
            for (int j = 0; j < 4; j++)
                vp[j] = 2.f * acc[i][j] - xm - xx[batX * blockIdx.z + n + j];
        } else {
            #pragma unroll
            for (int j = 0; j < 4; j++) vp[j] = acc[i][j];
        }
        *reinterpret_cast<float4*>(&C[(size_t)m * ldc + n]) = v;
    }
}

// ---------------- bf16x3 mma.sync m16n8k16 NT GEMM (dist / Y) ----------------
// C(MxN) = A(MxK) * B(NxK)^T, 3-term compensated bf16 (~17 mantissa bits).
// Block 128x128, 8 warps 2(m)x4(n), warp tile 64x32. Split at STS; double buffer.
__device__ __forceinline__ unsigned pkbf(float a, float b) {   // lo half=a, hi half=b
    unsigned r; asm("cvt.rn.bf16x2.f32 %0, %1, %2;" : "=r"(r) : "f"(b), "f"(a));
    return r;
}
__device__ __forceinline__ void split4(float4 v, unsigned& h0, unsigned& h1,
                                       unsigned& l0, unsigned& l1) {
    h0 = pkbf(v.x, v.y); h1 = pkbf(v.z, v.w);
    float hx = __uint_as_float(h0 << 16), hy = __uint_as_float(h0 & 0xFFFF0000u);
    float hz = __uint_as_float(h1 << 16), hw = __uint_as_float(h1 & 0xFFFF0000u);
    l0 = pkbf(v.x - hx, v.y - hy);
    l1 = pkbf(v.z - hz, v.w - hw);
}
#define MMA_BF16(c, a0,a1,a2,a3, b0,b1)                                        \
    asm volatile("mma.sync.aligned.m16n8k16.row.col.f32.bf16.bf16.f32 "         \
                 "{%0,%1,%2,%3}, {%4,%5,%6,%7}, {%8,%9}, {%0,%1,%2,%3};"        \
                 : "+f"(c[0]), "+f"(c[1]), "+f"(c[2]), "+f"(c[3])               \
                 : "r"(a0), "r"(a1), "r"(a2), "r"(a3), "r"(b0), "r"(b1))

__global__ void __launch_bounds__(256) gemm_bf16(int mode, int N, int sym,
        const float* __restrict__ A, int lda, int batA,
        const float* __restrict__ B, int ldb, int batB,
        float* __restrict__ C, int ldc, int batC, int K,
        const float* __restrict__ xx, int batX)
{
    if (sym && blockIdx.x > blockIdx.y) return;   // lower triangle only
    A += (size_t)blockIdx.z * batA;
    B += (size_t)blockIdx.z * batB;
    C += (size_t)blockIdx.z * batC;
    const float* xb = xx ? (xx + (size_t)batX * blockIdx.z) : xx;

    const int m0 = blockIdx.y * 128;
    const int n0 = blockIdx.x * 128;

    // [buf][mat: Ah,Al,Bh,Bl][row][kpair]; stride 12 u32 -> conflict-free frags. 48KB.
    __shared__ __align__(16) uint32_t SM[2][4][128][12];

    const int tid = threadIdx.x;
    const int w  = tid >> 5, l = tid & 31;
    const int g  = l >> 2,  t4 = l & 3;
    const int wm = (w & 1) * 64;
    const int wn = (w >> 1) * 32;
    const int lr = tid >> 2;          // 0..63
    const int lk = (tid & 3) * 4;     // k offset 0,4,8,12
    const int kp = (tid & 3) * 2;     // pair index 0,2,4,6

    float c[4][4][4];
    #pragma unroll
    for (int i = 0; i < 4; i++)
        #pragma unroll
        for (int j = 0; j < 4; j++)
            #pragma unroll
            for (int q = 0; q < 4; q++) c[i][j][q] = 0.f;

    const float4 z4 = {0.f, 0.f, 0.f, 0.f};
    float4 ra0, ra1, rb0, rb1;

    // prologue: load k-tile 0
    {
        const float* Ap = A + (size_t)(m0 + lr) * lda + lk;
        ra0 = *(const float4*)Ap;
        ra1 = *(const float4*)(Ap + (size_t)64 * lda);
        int nr0 = n0 + lr, nr1 = nr0 + 64;
        rb0 = (nr0 < N) ? *(const float4*)(B + (size_t)nr0 * ldb + lk) : z4;
        rb1 = (nr1 < N) ? *(const float4*)(B + (size_t)nr1 * ldb + lk) : z4;
    }

    const int T = K / 16;
    int p = 0;
    for (int t = 0; t < T; t++) {
        __syncthreads();   // previous tile's mma done with buffer p
        {
            unsigned h0, h1, l0, l1;
            split4(ra0, h0, h1, l0, l1);
            *(uint2*)&SM[p][0][lr][kp] = make_uint2(h0, h1);
            *(uint2*)&SM[p][1][lr][kp] = make_uint2(l0, l1);
            split4(ra1, h0, h1, l0, l1);
            *(uint2*)&SM[p][0][lr + 64][kp] = make_uint2(h0, h1);
            *(uint2*)&SM[p][1][lr + 64][kp] = make_uint2(l0, l1);
            split4(rb0, h0, h1, l0, l1);
            *(uint2*)&SM[p][2][lr][kp] = make_uint2(h0, h1);
            *(uint2*)&SM[p][3][lr][kp] = make_uint2(l0, l1);
            split4(rb1, h0, h1, l0, l1);
            *(uint2*)&SM[p][2][lr + 64][kp] = make_uint2(h0, h1);
            *(uint2*)&SM[p][3][lr + 64][kp] = make_uint2(l0, l1);
        }
        __syncthreads();
        if (t + 1 < T) {   // prefetch next tile (overlaps mma below)
            int k0 = (t + 1) * 16;
            const float* Ap = A + (size_t)(m0 + lr) * lda + k0 + lk;
            ra0 = *(const float4*)Ap;
            ra1 = *(const float4*)(Ap + (size_t)64 * lda);
            int nr0 = n0 + lr, nr1 = nr0 + 64;
            rb0 = (nr0 < N) ? *(const float4*)(B + (size_t)nr0 * ldb + k0 + lk) : z4;
            rb1 = (nr1 < N) ? *(const float4*)(B + (size_t)nr1 * ldb + k0 + lk) : z4;
        }
        {
            unsigned ah[4][4], al[4][4], bh[4][2], bl[4][2];
            #pragma unroll
            for (int mi = 0; mi < 4; mi++) {
                int r = wm + mi * 16 + g;
                ah[mi][0] = SM[p][0][r    ][t4];
                ah[mi][1] = SM[p][0][r + 8][t4];
                ah[mi][2] = SM[p][0][r    ][t4 + 4];
                ah[mi][3] = SM[p][0][r + 8][t4 + 4];
                al[mi][0] = SM[p][1][r    ][t4];
                al[mi][1] = SM[p][1][r + 8][t4];
                al[mi][2] = SM[p][1][r    ][t4 + 4];
                al[mi][3] = SM[p][1][r + 8][t4 + 4];
            }
            #pragma unroll
            for (int ni = 0; ni < 4; ni++) {
                int r = wn + ni * 8 + g;
                bh[ni][0] = SM[p][2][r][t4];
                bh[ni][1] = SM[p][2][r][t4 + 4];
                bl[ni][0] = SM[p][3][r][t4];
                bl[ni][1] = SM[p][3][r][t4 + 4];
            }
            #pragma unroll
            for (int mi = 0; mi < 4; mi++)
                #pragma unroll
                for (int ni = 0; ni < 4; ni++) {
                    float* cc = c[mi][ni];
                    MMA_BF16(cc, ah[mi][0], ah[mi][1], ah[mi][2], ah[mi][3],
                                 bl[ni][0], bl[ni][1]);
                    MMA_BF16(cc, al[mi][0], al[mi][1], al[mi][2], al[mi][3],
                                 bh[ni][0], bh[ni][1]);
                    MMA_BF16(cc, ah[mi][0], ah[mi][1], ah[mi][2], ah[mi][3],
                                 bh[ni][0], bh[ni][1]);
                }
        }
        p ^= 1;
    }

    // ---- normal epilogue ----
    #pragma unroll
    for (int mi = 0; mi < 4; mi++) {
        int r0 = m0 + wm + mi * 16 + g;
        int r1 = r0 + 8;
        float xm0 = 0.f, xm1 = 0.f;
        if (mode == 1) { xm0 = xb[r0]; xm1 = xb[r1]; }
        #pragma unroll
        for (int ni = 0; ni < 4; ni++) {
            int n = n0 + wn + ni * 8 + t4 * 2;
            if (n < N) {
                float v0 = c[mi][ni][0], v1 = c[mi][ni][1];
                float v2 = c[mi][ni][2], v3 = c[mi][ni][3];
                if (mode == 1) {
                    float xn0 = xb[n], xn1 = xb[n + 1];
                    v0 = 2.f * v0 - xm0 - xn0;  v1 = 2.f * v1 - xm0 - xn1;
                    v2 = 2.f * v2 - xm1 - xn0;  v3 = 2.f * v3 - xm1 - xn1;
                }
                float2 p0 = {v0, v1}, p1 = {v2, v3};
                *(float2*)&C[(size_t)r0 * ldc + n] = p0;
                *(float2*)&C[(size_t)r1 * ldc + n] = p1;
            }
        }
    }

    // ---- mirror epilogue (sym, strictly lower blocks): C[n][m] via smem transpose ----
    if (sym && blockIdx.x < blockIdx.y) {
        float (*st)[132] = reinterpret_cast<float(*)[132]>(&SM[0][0][0][0]); // 16.9KB < 48KB
        #pragma unroll 1
        for (int s = 0; s < 4; s++) {
            __syncthreads();
            #pragma unroll
            for (int mi = 0; mi < 4; mi++) {
                int r0l = wm + mi * 16 + g;
                int r0 = m0 + r0l, r1 = r0 + 8;
                int n  = n0 + wn + s * 8 + t4 * 2;
                float xm0 = xb[r0], xm1 = xb[r1];
                float xn0 = xb[n],  xn1 = xb[n + 1];
                float v0 = 2.f * c[mi][s][0] - xm0 - xn0;
                float v1 = 2.f * c[mi][s][1] - xm0 - xn1;
                float v2 = 2.f * c[mi][s][2] - xm1 - xn0;
                float v3 = 2.f * c[mi][s][3] - xm1 - xn1;
                int cl = (w >> 1) * 8 + t4 * 2;
                st[cl    ][r0l]     = v0;
                st[cl + 1][r0l]     = v1;
                st[cl    ][r0l + 8] = v2;
                st[cl + 1][r0l + 8] = v3;
            }
            __syncthreads();
            int rsel = tid >> 3;
            int wnq = rsel >> 3, off = rsel & 7;
            int nl = wnq * 32 + s * 8 + off;
            int colm = (tid & 7) * 16;
            float* dst = &C[(size_t)(n0 + nl) * ldc + m0 + colm];
            const float* src = &st[rsel][colm];
            #pragma unroll
            for (int q = 0; q < 4; q++)
                *(float4*)(dst + q * 4) = *(const float4*)(src + q * 4);
        }
    }
}

// ---------------- plain-tf32 GEMM with fused BN/ELU + pooling (conv5 only) ----------------
__device__ __forceinline__ unsigned f2tf(float f) {
    unsigned u; asm("cvt.rna.tf32.f32 %0, %1;" : "=r"(u) : "f"(f)); return u;
}
__device__ __forceinline__ void cp16(void* dst, const void* src, int sz) {
    unsigned d = (unsigned)__cvta_generic_to_shared(dst);
    asm volatile("cp.async.ca.shared.global [%0], [%1], 16, %2;"
                 :: "r"(d), "l"(src), "r"(sz));
}
#define MMA_TF32(c, a0,a1,a2,a3, b0,b1)                                        \
    asm volatile("mma.sync.aligned.m16n8k8.row.col.f32.tf32.tf32.f32 "          \
                 "{%0,%1,%2,%3}, {%4,%5,%6,%7}, {%8,%9}, {%0,%1,%2,%3};"        \
                 : "+f"(c[0]), "+f"(c[1]), "+f"(c[2]), "+f"(c[3])               \
                 : "r"(a0), "r"(a1), "r"(a2), "r"(a3), "r"(b0), "r"(b1))

__global__ void __launch_bounds__(256) conv5_tf32(
        const float* __restrict__ A, int lda,
        const float* __restrict__ B, int ldb, int K,
        const float* __restrict__ gg, const float* __restrict__ bb,
        float* __restrict__ pomax, float* __restrict__ posum)
{
    const int m0 = blockIdx.y * 128;
    const int n0 = blockIdx.x * 128;

    __shared__ __align__(16) float As[2][128][20];
    __shared__ __align__(16) float Bs[2][128][20];

    const int tid = threadIdx.x;
    const int w  = tid >> 5, l = tid & 31;
    const int g  = l >> 2,  t4 = l & 3;
    const int wm = (w & 1) * 64;
    const int wn = (w >> 1) * 32;
    const int lr = tid >> 2;
    const int lk = (tid & 3) * 4;

    float c[4][4][4];
    #pragma unroll
    for (int i = 0; i < 4; i++)
        #pragma unroll
        for (int j = 0; j < 4; j++)
            #pragma unroll
            for (int q = 0; q < 4; q++) c[i][j][q] = 0.f;

    #define LOAD_TILE(buf, k0)                                                  \
    {                                                                           \
        const float* Ap = A + (size_t)(m0 + lr) * lda + (k0) + lk;              \
        cp16(&As[buf][lr][lk],      Ap, 16);                                    \
        cp16(&As[buf][lr + 64][lk], Ap + (size_t)64 * lda, 16);                 \
        const float* Bp = B + (size_t)(n0 + lr) * ldb + (k0) + lk;              \
        cp16(&Bs[buf][lr][lk],      Bp, 16);                                    \
        cp16(&Bs[buf][lr + 64][lk], Bp + (size_t)64 * ldb, 16);                 \
        asm volatile("cp.async.commit_group;");                                 \
    }

    LOAD_TILE(0, 0);
    asm volatile("cp.async.wait_group 0;" ::: "memory");
    __syncthreads();

    const int T = K / 16;
    int p = 0;
    for (int t = 0; t < T; t++) {
        if (t + 1 < T) LOAD_TILE(p ^ 1, (t + 1) * 16);
        #pragma unroll
        for (int kk = 0; kk < 16; kk += 8) {
            unsigned ah[4][4], bh[4][2];
            #pragma unroll
            for (int mi = 0; mi < 4; mi++) {
                int r = wm + mi * 16 + g;
                ah[mi][0] = f2tf(As[p][r    ][kk + t4]);
                ah[mi][1] = f2tf(As[p][r + 8][kk + t4]);
                ah[mi][2] = f2tf(As[p][r    ][kk + t4 + 4]);
                ah[mi][3] = f2tf(As[p][r + 8][kk + t4 + 4]);
            }
            #pragma unroll
            for (int ni = 0; ni < 4; ni++) {
                int r = wn + ni * 8 + g;
                bh[ni][0] = f2tf(Bs[p][r][kk + t4]);
                bh[ni][1] = f2tf(Bs[p][r][kk + t4 + 4]);
            }
            #pragma unroll
            for (int mi = 0; mi < 4; mi++)
                #pragma unroll
                for (int ni = 0; ni < 4; ni++)
                    MMA_TF32(c[mi][ni], ah[mi][0], ah[mi][1], ah[mi][2], ah[mi][3],
                             bh[ni][0], bh[ni][1]);
        }
        if (t + 1 < T) {
            asm volatile("cp.async.wait_group 0;" ::: "memory");
            __syncthreads();
            p ^= 1;
        }
    }
    #undef LOAD_TILE

    // fused BN/ELU + max/sum pooling over the block's 128 rows
    __syncthreads();
    float* pm = &As[0][0][0];      // [2][128]
    float* ps = pm + 256;
    #pragma unroll
    for (int ni = 0; ni < 4; ni++) {
        #pragma unroll
        for (int j = 0; j < 2; j++) {
            int cl = wn + ni * 8 + t4 * 2 + j;
            int n  = n0 + cl;
            float sc = gg[n] * BN_SCALE, bv = bb[n];
            float vmax = -INFINITY, vsum = 0.f;
            #pragma unroll
            for (int mi = 0; mi < 4; mi++) {
                float va = fmaf(sc, c[mi][ni][j],     bv);
                va = (va > 0.f) ? va : expm1f(va);
                float vb = fmaf(sc, c[mi][ni][j + 2], bv);
                vb = (vb > 0.f) ? vb : expm1f(vb);
                vmax = fmaxf(vmax, fmaxf(va, vb));
                vsum += va + vb;
            }
            #pragma unroll
            for (int off = 4; off <= 16; off <<= 1) {
                vmax = fmaxf(vmax, __shfl_xor_sync(0xffffffffu, vmax, off));
                vsum += __shfl_xor_sync(0xffffffffu, vsum, off);
            }
            if (g == 0) {
                pm[(w & 1) * 128 + cl] = vmax;
                ps[(w & 1) * 128 + cl] = vsum;
            }
        }
    }
    __syncthreads();
    if (tid < 128) {
        int o = blockIdx.y * 1024 + n0 + tid;
        pomax[o] = fmaxf(pm[tid], pm[128 + tid]);
        posum[o] = ps[tid] + ps[128 + tid];
    }
}

// ---------------- top-k (k=20): u64 keys, cached top-3 tournament ----------------
__global__ void __launch_bounds__(256) topk_kernel(
        const float* __restrict__ D, int* __restrict__ out) {
    int warp = (blockIdx.x * blockDim.x + threadIdx.x) >> 5;
    int lane = threadIdx.x & 31;
    const float* row = D + (size_t)warp * NP;
    unsigned long long k[32];
    #pragma unroll
    for (int j = 0; j < 32; j++) {
        int idx = lane + j * 32;
        unsigned u = __float_as_uint(row[idx]);
        unsigned o = (u & 0x80000000u) ? ~u : (u | 0x80000000u);
        k[j] = ((unsigned long long)o << 32) | (unsigned)(1023 - idx);
    }
    int base = warp & ~(NP - 1);
    unsigned long long s0 = 0, s1 = 0, s2 = 0;
    #pragma unroll
    for (int j = 0; j < 32; j++) {
        unsigned long long x = k[j];
        if (x > s0)      { s2 = s1; s1 = s0; s0 = x; }
        else if (x > s1) { s2 = s1; s1 = x; }
        else if (x > s2) { s2 = x; }
    }
    for (int it = 0; it < KNN; it++) {
        unsigned long long wv = s0;
        #pragma unroll
        for (int off = 16; off; off >>= 1) {
            unsigned long long o = __shfl_xor_sync(0xffffffffu, wv, off);
            if (o > wv) wv = o;
        }
        if (s0 == wv) {
            s0 = s1; s1 = s2; s2 = 0;
            if (s0 == 0) {
                #pragma unroll
                for (int j = 0; j < 32; j++) {
                    unsigned long long x = k[j];
                    if (x < wv) {
                        if (x > s0)      { s2 = s1; s1 = s0; s0 = x; }
                        else if (x > s1) { s2 = s1; s1 = x; }
                        else if (x > s2) { s2 = x; }
                    }
                }
            }
        }
        if (lane == 0) out[warp * KNN + it] = base + 1023 - (int)(wv & 1023u);
    }
}

// ---------------- edge-conv aggregation (+ fused rowsum for next layer) ----------------
__global__ void __launch_bounds__(256) aggregate_kernel(
        const float* __restrict__ Yn, const float* __restrict__ Yc,
        int C, const int* __restrict__ idx,
        const float* __restrict__ gg, const float* __restrict__ bb,
        float* __restrict__ outp, float* __restrict__ xxout) {
    int r = blockIdx.x;
    int c = threadIdx.x;
    __shared__ int sidx[KNN];
    __shared__ float red[256];
    if (c < KNN) sidx[c] = idx[r * KNN + c];
    __syncthreads();
    float vmax = -INFINITY, vmin = INFINITY;
    #pragma unroll 4
    for (int j = 0; j < KNN; j++) {
        float v = Yn[(size_t)sidx[j] * C + c];
        vmax = fmaxf(vmax, v);
        vmin = fminf(vmin, v);
    }
    float center = Yc[(size_t)r * C + c] - Yn[(size_t)r * C + c];
    float s = gg[c] * BN_SCALE;
    float h = s * ((s >= 0.f ? vmax : vmin) + center) + bb[c];
    float e = (h > 0.f) ? h : expm1f(h);
    outp[(size_t)r * 512 + c] = e;
    if (xxout) {
        red[c] = e * e;
        __syncthreads();
        for (int st = blockDim.x >> 1; st > 0; st >>= 1) {
            if (c < st) red[c] += red[c + st];
            __syncthreads();
        }
        if (c == 0) xxout[r] = red[0];
    }
}

// ---------------- pooling combine ----------------
__global__ void __launch_bounds__(256) pool_combine(
        const float* __restrict__ pmax, const float* __restrict__ psum,
        float* __restrict__ f) {
    int t = blockIdx.x * 256 + threadIdx.x;
    if (t >= NB * 1024) return;
    int b = t >> 10, o = t & 1023;
    float m = -INFINITY, s = 0.f;
    for (int c = 0; c < 8; c++) {
        m = fmaxf(m, pmax[(b * 8 + c) * 1024 + o]);
        s += psum[(b * 8 + c) * 1024 + o];
    }
    f[b * 2048 + o] = m;
    f[b * 2048 + 1024 + o] = s * (1.f / 1024.f);
}

// ---------------- tiny MLP: one warp per output element ----------------
__global__ void __launch_bounds__(256) mlp_kernel(
        const float* __restrict__ in, int Kd,
        const float* __restrict__ W,
        const float* __restrict__ gg, const float* __restrict__ bb,
        float* __restrict__ out, int Nout, int rows, int bnelu) {
    int wid  = (blockIdx.x * blockDim.x + threadIdx.x) >> 5;
    int lane = threadIdx.x & 31;
    if (wid >= rows * Nout) return;
    int r = wid / Nout, o = wid % Nout;
    const float* a = in + (size_t)r * Kd;
    const float* w = W  + (size_t)o * Kd;
    float s = 0.f;
    for (int k = lane; k < Kd; k += 32) s += a[k] * w[k];
    #pragma unroll
    for (int off = 16; off; off >>= 1) s += __shfl_xor_sync(0xffffffffu, s, off);
    if (lane == 0) {
        float v;
        if (bnelu) {
            float sc = gg[o] * BN_SCALE;
            v = fmaf(sc, s, bb[o]);
            v = (v > 0.f) ? v : expm1f(v);
        } else {
            v = s + bb[o];
        }
        out[(size_t)r * Nout + o] = v;
    }
}

extern "C" void kernel_launch(void* const* d_in, const int* in_sizes, int n_in,
                              void* d_out, int out_size) {
    const float* x   = (const float*)d_in[0];
    const float* W1  = (const float*)d_in[1];
    const float* g1  = (const float*)d_in[2];
    const float* b1  = (const float*)d_in[3];
    const float* W2  = (const float*)d_in[4];
    const float* g2  = (const float*)d_in[5];
    const float* b2  = (const float*)d_in[6];
    const float* W3  = (const float*)d_in[7];
    const float* g3  = (const float*)d_in[8];
    const float* b3  = (const float*)d_in[9];
    const float* W4  = (const float*)d_in[10];
    const float* g4  = (const float*)d_in[11];
    const float* b4  = (const float*)d_in[12];
    const float* W5  = (const float*)d_in[13];
    const float* g5  = (const float*)d_in[14];
    const float* b5  = (const float*)d_in[15];
    const float* Wl1 = (const float*)d_in[16];
    const float* gl1 = (const float*)d_in[17];
    const float* bl1 = (const float*)d_in[18];
    const float* Wl2 = (const float*)d_in[19];
    const float* gl2 = (const float*)d_in[20];
    const float* bl2 = (const float*)d_in[21];
    const float* Wl3 = (const float*)d_in[22];
    const float* bl3 = (const float*)d_in[23];

    float *dist, *cat, *Y, *xx, *pmax, *psum, *f, *f1, *f2;
    int* idx;
    cudaGetSymbolAddress((void**)&dist, g_dist);
    cudaGetSymbolAddress((void**)&cat,  g_cat);
    cudaGetSymbolAddress((void**)&Y,    g_Y);
    cudaGetSymbolAddress((void**)&xx,   g_xx);
    cudaGetSymbolAddress((void**)&idx,  g_idx);
    cudaGetSymbolAddress((void**)&pmax, g_pmax);
    cudaGetSymbolAddress((void**)&psum, g_psum);
    cudaGetSymbolAddress((void**)&f,    g_f);
    cudaGetSymbolAddress((void**)&f1,   g_f1);
    cudaGetSymbolAddress((void**)&f2,   g_f2);

    dim3 blk(16, 16);

    // ---------- layer 1 (fp32, K=3) ----------
    rowsum_kernel<<<NR / 256, 256>>>(x, 3, 3, xx);
    gemm_nt<<<dim3(NP / 64, NP / 64, NB), blk>>>(1, x, 3, NP * 3, x, 3, NP * 3,
                                                 dist, NP, NP * NP, 3, xx, NP);
    topk_kernel<<<NR / 8, 256>>>(dist, idx);
    gemm_nt<<<dim3(1, NR / 64, 2), blk>>>(0, x, 3, 0, W1, 6, 3,
                                          Y, 64, NR * 64, 3, nullptr, 0);
    aggregate_kernel<<<NR, 64>>>(Y, Y + (size_t)NR * 64, 64, idx, g1, b1, cat + 0, xx);

    // ---------- layers 2-4 (bf16x3 m16n8k16) ----------
    struct { const float* X; int Cin; const float* W; const float* g; const float* b;
             int Cout; int off; } L[3] = {
        { cat + 0,   64,  W2, g2, b2,  64,  64 },
        { cat + 64,  64,  W3, g3, b3, 128, 128 },
        { cat + 128, 128, W4, g4, b4, 256, 256 },
    };
    for (int li = 0; li < 3; li++) {
        gemm_bf16<<<dim3(NP / 128, NP / 128, NB), 256>>>(1, NP, 1,
            L[li].X, 512, NP * 512, L[li].X, 512, NP * 512,
            dist, NP, NP * NP, L[li].Cin, xx, NP);
        topk_kernel<<<NR / 8, 256>>>(dist, idx);
        gemm_bf16<<<dim3((L[li].Cout + 127) / 128, NR / 128, 2), 256>>>(0, L[li].Cout, 0,
            L[li].X, 512, 0, L[li].W, 2 * L[li].Cin, L[li].Cin,
            Y, L[li].Cout, NR * L[li].Cout, L[li].Cin, nullptr, 0);
        aggregate_kernel<<<NR, L[li].Cout>>>(Y, Y + (size_t)NR * L[li].Cout,
            L[li].Cout, idx, L[li].g, L[li].b, cat + L[li].off,
            (li < 2) ? xx : nullptr);
    }

    // ---------- conv5: plain tf32, fused BN/ELU + pooling partials ----------
    conv5_tf32<<<dim3(1024 / 128, NR / 128), 256>>>(cat, 512, W5, 512, 512,
                                                    g5, b5, pmax, psum);

    // ---------- pooling combine + MLP head ----------
    pool_combine<<<32, 256>>>(pmax, psum, f);
    mlp_kernel<<<512, 256>>>(f,  2048, Wl1, gl1, bl1, f1, 512, NB, 1);
    mlp_kernel<<<256, 256>>>(f1, 512,  Wl2, gl2, bl2, f2, 256, NB, 1);
    mlp_kernel<<<40,  256>>>(f2, 256,  Wl3, nullptr, bl3, (float*)d_out, 40, NB, 0);
}

// round 14
// speedup vs baseline: 1.9442x; 1.1007x over previous
#include <cuda_runtime.h>
#include <stdint.h>
#include <math.h>

#define BN_SCALE 0.99999500003749972f

#define NB 8
#define NP 1024
#define NR (NB*NP)     // 8192 rows total
#define KNN 20

// ---------------- static scratch (no allocations allowed) ----------------
__device__ __align__(16) float g_dist[(size_t)NR * NP];   // 32MB (dist, layers 2-4)
__device__ __align__(16) float g_cat [(size_t)NR * 512];  // x1|x2|x3|x4 concatenated
__device__ __align__(16) float g_Y   [(size_t)2 * NR * 256];  // Yn | Yc (z-batched)
__device__ float g_xx[NR];
__device__ int   g_idx[NR * KNN];
__device__ float g_pmax[64 * 1024];
__device__ float g_psum[64 * 1024];
__device__ float g_f [NB * 2048];
__device__ float g_f1[NB * 512];
__device__ float g_f2[NB * 256];

// ---------------- fp32 NT GEMM (layer-1 Y only, K=3) ----------------
__global__ void __launch_bounds__(256) gemm_nt(int mode,
                        const float* __restrict__ A, int lda, int batA,
                        const float* __restrict__ B, int ldb, int batB,
                        float* __restrict__ C, int ldc, int batC, int K,
                        const float* __restrict__ xx, int batX)
{
    A += (size_t)blockIdx.z * batA;
    B += (size_t)blockIdx.z * batB;
    C += (size_t)blockIdx.z * batC;
    const int m0 = blockIdx.y * 64;
    const int n0 = blockIdx.x * 64;
    __shared__ __align__(16) float As[16][64];
    __shared__ __align__(16) float Bs[16][64];
    const int tx = threadIdx.x, ty = threadIdx.y;
    const int t = ty * 16 + tx;
    const int lm = t >> 2;
    const int lk = (t & 3) * 4;
    float acc[4][4] = {};
    for (int k0 = 0; k0 < K; k0 += 16) {
        #pragma unroll
        for (int u = 0; u < 4; u++) {
            int kk = lk + u;
            As[kk][lm] = (k0 + kk < K) ? A[(size_t)(m0 + lm) * lda + k0 + kk] : 0.f;
            Bs[kk][lm] = (k0 + kk < K) ? B[(size_t)(n0 + lm) * ldb + k0 + kk] : 0.f;
        }
        __syncthreads();
        #pragma unroll
        for (int kk = 0; kk < 16; kk++) {
            float4 a4 = *reinterpret_cast<const float4*>(&As[kk][ty * 4]);
            float4 b4 = *reinterpret_cast<const float4*>(&Bs[kk][tx * 4]);
            float a[4] = {a4.x, a4.y, a4.z, a4.w};
            float b[4] = {b4.x, b4.y, b4.z, b4.w};
            #pragma unroll
            for (int i = 0; i < 4; i++)
                #pragma unroll
                for (int j = 0; j < 4; j++)
                    acc[i][j] = fmaf(a[i], b[j], acc[i][j]);
        }
        __syncthreads();
    }
    #pragma unroll
    for (int i = 0; i < 4; i++) {
        int m = m0 + ty * 4 + i;
        int n = n0 + tx * 4;
        float4 v; float* vp = &v.x;
        if (mode == 1) {
            float xm = xx[batX * blockIdx.z + m];
            #pragma unroll
            for (int j = 0; j < 4; j++)
                vp[j] = 2.f * acc[i][j] - xm - xx[batX * blockIdx.z + n + j];
        } else {
            #pragma unroll
            for (int j = 0; j < 4; j++) vp[j] = acc[i][j];
        }
        *reinterpret_cast<float4*>(&C[(size_t)m * ldc + n]) = v;
    }
}

// ---------------- bf16x3 mma.sync m16n8k16 NT GEMM (dist / Y, layers 2-4) ----------------
__device__ __forceinline__ unsigned pkbf(float a, float b) {   // lo half=a, hi half=b
    unsigned r; asm("cvt.rn.bf16x2.f32 %0, %1, %2;" : "=r"(r) : "f"(b), "f"(a));
    return r;
}
__device__ __forceinline__ void split4(float4 v, unsigned& h0, unsigned& h1,
                                       unsigned& l0, unsigned& l1) {
    h0 = pkbf(v.x, v.y); h1 = pkbf(v.z, v.w);
    float hx = __uint_as_float(h0 << 16), hy = __uint_as_float(h0 & 0xFFFF0000u);
    float hz = __uint_as_float(h1 << 16), hw = __uint_as_float(h1 & 0xFFFF0000u);
    l0 = pkbf(v.x - hx, v.y - hy);
    l1 = pkbf(v.z - hz, v.w - hw);
}
#define MMA_BF16(c, a0,a1,a2,a3, b0,b1)                                        \
    asm volatile("mma.sync.aligned.m16n8k16.row.col.f32.bf16.bf16.f32 "         \
                 "{%0,%1,%2,%3}, {%4,%5,%6,%7}, {%8,%9}, {%0,%1,%2,%3};"        \
                 : "+f"(c[0]), "+f"(c[1]), "+f"(c[2]), "+f"(c[3])               \
                 : "r"(a0), "r"(a1), "r"(a2), "r"(a3), "r"(b0), "r"(b1))

__global__ void __launch_bounds__(256) gemm_bf16(int mode, int N, int sym,
        const float* __restrict__ A, int lda, int batA,
        const float* __restrict__ B, int ldb, int batB,
        float* __restrict__ C, int ldc, int batC, int K,
        const float* __restrict__ xx, int batX)
{
    if (sym && blockIdx.x > blockIdx.y) return;   // lower triangle only
    A += (size_t)blockIdx.z * batA;
    B += (size_t)blockIdx.z * batB;
    C += (size_t)blockIdx.z * batC;
    const float* xb = xx ? (xx + (size_t)batX * blockIdx.z) : xx;

    const int m0 = blockIdx.y * 128;
    const int n0 = blockIdx.x * 128;

    __shared__ __align__(16) uint32_t SM[2][4][128][12];   // Ah,Al,Bh,Bl; 48KB

    const int tid = threadIdx.x;
    const int w  = tid >> 5, l = tid & 31;
    const int g  = l >> 2,  t4 = l & 3;
    const int wm = (w & 1) * 64;
    const int wn = (w >> 1) * 32;
    const int lr = tid >> 2;
    const int lk = (tid & 3) * 4;
    const int kp = (tid & 3) * 2;

    float c[4][4][4];
    #pragma unroll
    for (int i = 0; i < 4; i++)
        #pragma unroll
        for (int j = 0; j < 4; j++)
            #pragma unroll
            for (int q = 0; q < 4; q++) c[i][j][q] = 0.f;

    const float4 z4 = {0.f, 0.f, 0.f, 0.f};
    float4 ra0, ra1, rb0, rb1;

    {
        const float* Ap = A + (size_t)(m0 + lr) * lda + lk;
        ra0 = *(const float4*)Ap;
        ra1 = *(const float4*)(Ap + (size_t)64 * lda);
        int nr0 = n0 + lr, nr1 = nr0 + 64;
        rb0 = (nr0 < N) ? *(const float4*)(B + (size_t)nr0 * ldb + lk) : z4;
        rb1 = (nr1 < N) ? *(const float4*)(B + (size_t)nr1 * ldb + lk) : z4;
    }

    const int T = K / 16;
    int p = 0;
    for (int t = 0; t < T; t++) {
        __syncthreads();
        {
            unsigned h0, h1, l0, l1;
            split4(ra0, h0, h1, l0, l1);
            *(uint2*)&SM[p][0][lr][kp] = make_uint2(h0, h1);
            *(uint2*)&SM[p][1][lr][kp] = make_uint2(l0, l1);
            split4(ra1, h0, h1, l0, l1);
            *(uint2*)&SM[p][0][lr + 64][kp] = make_uint2(h0, h1);
            *(uint2*)&SM[p][1][lr + 64][kp] = make_uint2(l0, l1);
            split4(rb0, h0, h1, l0, l1);
            *(uint2*)&SM[p][2][lr][kp] = make_uint2(h0, h1);
            *(uint2*)&SM[p][3][lr][kp] = make_uint2(l0, l1);
            split4(rb1, h0, h1, l0, l1);
            *(uint2*)&SM[p][2][lr + 64][kp] = make_uint2(h0, h1);
            *(uint2*)&SM[p][3][lr + 64][kp] = make_uint2(l0, l1);
        }
        __syncthreads();
        if (t + 1 < T) {
            int k0 = (t + 1) * 16;
            const float* Ap = A + (size_t)(m0 + lr) * lda + k0 + lk;
            ra0 = *(const float4*)Ap;
            ra1 = *(const float4*)(Ap + (size_t)64 * lda);
            int nr0 = n0 + lr, nr1 = nr0 + 64;
            rb0 = (nr0 < N) ? *(const float4*)(B + (size_t)nr0 * ldb + k0 + lk) : z4;
            rb1 = (nr1 < N) ? *(const float4*)(B + (size_t)nr1 * ldb + k0 + lk) : z4;
        }
        {
            unsigned ah[4][4], al[4][4], bh[4][2], bl[4][2];
            #pragma unroll
            for (int mi = 0; mi < 4; mi++) {
                int r = wm + mi * 16 + g;
                ah[mi][0] = SM[p][0][r    ][t4];
                ah[mi][1] = SM[p][0][r + 8][t4];
                ah[mi][2] = SM[p][0][r    ][t4 + 4];
                ah[mi][3] = SM[p][0][r + 8][t4 + 4];
                al[mi][0] = SM[p][1][r    ][t4];
                al[mi][1] = SM[p][1][r + 8][t4];
                al[mi][2] = SM[p][1][r    ][t4 + 4];
                al[mi][3] = SM[p][1][r + 8][t4 + 4];
            }
            #pragma unroll
            for (int ni = 0; ni < 4; ni++) {
                int r = wn + ni * 8 + g;
                bh[ni][0] = SM[p][2][r][t4];
                bh[ni][1] = SM[p][2][r][t4 + 4];
                bl[ni][0] = SM[p][3][r][t4];
                bl[ni][1] = SM[p][3][r][t4 + 4];
            }
            #pragma unroll
            for (int mi = 0; mi < 4; mi++)
                #pragma unroll
                for (int ni = 0; ni < 4; ni++) {
                    float* cc = c[mi][ni];
                    MMA_BF16(cc, ah[mi][0], ah[mi][1], ah[mi][2], ah[mi][3],
                                 bl[ni][0], bl[ni][1]);
                    MMA_BF16(cc, al[mi][0], al[mi][1], al[mi][2], al[mi][3],
                                 bh[ni][0], bh[ni][1]);
                    MMA_BF16(cc, ah[mi][0], ah[mi][1], ah[mi][2], ah[mi][3],
                                 bh[ni][0], bh[ni][1]);
                }
        }
        p ^= 1;
    }

    // ---- normal epilogue ----
    #pragma unroll
    for (int mi = 0; mi < 4; mi++) {
        int r0 = m0 + wm + mi * 16 + g;
        int r1 = r0 + 8;
        float xm0 = 0.f, xm1 = 0.f;
        if (mode == 1) { xm0 = xb[r0]; xm1 = xb[r1]; }
        #pragma unroll
        for (int ni = 0; ni < 4; ni++) {
            int n = n0 + wn + ni * 8 + t4 * 2;
            if (n < N) {
                float v0 = c[mi][ni][0], v1 = c[mi][ni][1];
                float v2 = c[mi][ni][2], v3 = c[mi][ni][3];
                if (mode == 1) {
                    float xn0 = xb[n], xn1 = xb[n + 1];
                    v0 = 2.f * v0 - xm0 - xn0;  v1 = 2.f * v1 - xm0 - xn1;
                    v2 = 2.f * v2 - xm1 - xn0;  v3 = 2.f * v3 - xm1 - xn1;
                }
                float2 p0 = {v0, v1}, p1 = {v2, v3};
                *(float2*)&C[(size_t)r0 * ldc + n] = p0;
                *(float2*)&C[(size_t)r1 * ldc + n] = p1;
            }
        }
    }

    // ---- mirror epilogue (sym, strictly lower blocks) ----
    if (sym && blockIdx.x < blockIdx.y) {
        float (*st)[132] = reinterpret_cast<float(*)[132]>(&SM[0][0][0][0]);
        #pragma unroll 1
        for (int s = 0; s < 4; s++) {
            __syncthreads();
            #pragma unroll
            for (int mi = 0; mi < 4; mi++) {
                int r0l = wm + mi * 16 + g;
                int r0 = m0 + r0l, r1 = r0 + 8;
                int n  = n0 + wn + s * 8 + t4 * 2;
                float xm0 = xb[r0], xm1 = xb[r1];
                float xn0 = xb[n],  xn1 = xb[n + 1];
                float v0 = 2.f * c[mi][s][0] - xm0 - xn0;
                float v1 = 2.f * c[mi][s][1] - xm0 - xn1;
                float v2 = 2.f * c[mi][s][2] - xm1 - xn0;
                float v3 = 2.f * c[mi][s][3] - xm1 - xn1;
                int cl = (w >> 1) * 8 + t4 * 2;
                st[cl    ][r0l]     = v0;
                st[cl + 1][r0l]     = v1;
                st[cl    ][r0l + 8] = v2;
                st[cl + 1][r0l + 8] = v3;
            }
            __syncthreads();
            int rsel = tid >> 3;
            int wnq = rsel >> 3, off = rsel & 7;
            int nl = wnq * 32 + s * 8 + off;
            int colm = (tid & 7) * 16;
            float* dst = &C[(size_t)(n0 + nl) * ldc + m0 + colm];
            const float* src = &st[rsel][colm];
            #pragma unroll
            for (int q = 0; q < 4; q++)
                *(float4*)(dst + q * 4) = *(const float4*)(src + q * 4);
        }
    }
}

// ---------------- fp16 single m16n8k16 conv5 + fused BN/ELU + pooling ----------------
__device__ __forceinline__ unsigned pkhf(float a, float b) {   // lo half=a, hi half=b
    unsigned r; asm("cvt.rn.f16x2.f32 %0, %1, %2;" : "=r"(r) : "f"(b), "f"(a));
    return r;
}
#define MMA_FP16(c, a0,a1,a2,a3, b0,b1)                                        \
    asm volatile("mma.sync.aligned.m16n8k16.row.col.f32.f16.f16.f32 "           \
                 "{%0,%1,%2,%3}, {%4,%5,%6,%7}, {%8,%9}, {%0,%1,%2,%3};"        \
                 : "+f"(c[0]), "+f"(c[1]), "+f"(c[2]), "+f"(c[3])               \
                 : "r"(a0), "r"(a1), "r"(a2), "r"(a3), "r"(b0), "r"(b1))

__global__ void __launch_bounds__(256) conv5_fp16(
        const float* __restrict__ A, int lda,
        const float* __restrict__ B, int ldb, int K,
        const float* __restrict__ gg, const float* __restrict__ bb,
        float* __restrict__ pomax, float* __restrict__ posum)
{
    const int m0 = blockIdx.y * 128;
    const int n0 = blockIdx.x * 128;

    __shared__ __align__(16) uint32_t SM[2][2][128][12];   // A,B fp16 pairs; 24KB

    const int tid = threadIdx.x;
    const int w  = tid >> 5, l = tid & 31;
    const int g  = l >> 2,  t4 = l & 3;
    const int wm = (w & 1) * 64;
    const int wn = (w >> 1) * 32;
    const int lr = tid >> 2;
    const int lk = (tid & 3) * 4;
    const int kp = (tid & 3) * 2;

    float c[4][4][4];
    #pragma unroll
    for (int i = 0; i < 4; i++)
        #pragma unroll
        for (int j = 0; j < 4; j++)
            #pragma unroll
            for (int q = 0; q < 4; q++) c[i][j][q] = 0.f;

    float4 ra0, ra1, rb0, rb1;
    {
        const float* Ap = A + (size_t)(m0 + lr) * lda + lk;
        ra0 = *(const float4*)Ap;
        ra1 = *(const float4*)(Ap + (size_t)64 * lda);
        const float* Bp = B + (size_t)(n0 + lr) * ldb + lk;
        rb0 = *(const float4*)Bp;
        rb1 = *(const float4*)(Bp + (size_t)64 * ldb);
    }

    const int T = K / 16;
    int p = 0;
    for (int t = 0; t < T; t++) {
        __syncthreads();
        *(uint2*)&SM[p][0][lr][kp]      = make_uint2(pkhf(ra0.x, ra0.y), pkhf(ra0.z, ra0.w));
        *(uint2*)&SM[p][0][lr + 64][kp] = make_uint2(pkhf(ra1.x, ra1.y), pkhf(ra1.z, ra1.w));
        *(uint2*)&SM[p][1][lr][kp]      = make_uint2(pkhf(rb0.x, rb0.y), pkhf(rb0.z, rb0.w));
        *(uint2*)&SM[p][1][lr + 64][kp] = make_uint2(pkhf(rb1.x, rb1.y), pkhf(rb1.z, rb1.w));
        __syncthreads();
        if (t + 1 < T) {
            int k0 = (t + 1) * 16;
            const float* Ap = A + (size_t)(m0 + lr) * lda + k0 + lk;
            ra0 = *(const float4*)Ap;
            ra1 = *(const float4*)(Ap + (size_t)64 * lda);
            const float* Bp = B + (size_t)(n0 + lr) * ldb + k0 + lk;
            rb0 = *(const float4*)Bp;
            rb1 = *(const float4*)(Bp + (size_t)64 * ldb);
        }
        {
            unsigned ah[4][4], bh[4][2];
            #pragma unroll
            for (int mi = 0; mi < 4; mi++) {
                int r = wm + mi * 16 + g;
                ah[mi][0] = SM[p][0][r    ][t4];
                ah[mi][1] = SM[p][0][r + 8][t4];
                ah[mi][2] = SM[p][0][r    ][t4 + 4];
                ah[mi][3] = SM[p][0][r + 8][t4 + 4];
            }
            #pragma unroll
            for (int ni = 0; ni < 4; ni++) {
                int r = wn + ni * 8 + g;
                bh[ni][0] = SM[p][1][r][t4];
                bh[ni][1] = SM[p][1][r][t4 + 4];
            }
            #pragma unroll
            for (int mi = 0; mi < 4; mi++)
                #pragma unroll
                for (int ni = 0; ni < 4; ni++)
                    MMA_FP16(c[mi][ni], ah[mi][0], ah[mi][1], ah[mi][2], ah[mi][3],
                             bh[ni][0], bh[ni][1]);
        }
        p ^= 1;
    }

    // fused BN/ELU + max/sum pooling over the block's 128 rows
    __syncthreads();
    float* pm = (float*)&SM[0][0][0][0];   // [2][128]
    float* ps = pm + 256;
    #pragma unroll
    for (int ni = 0; ni < 4; ni++) {
        #pragma unroll
        for (int j = 0; j < 2; j++) {
            int cl = wn + ni * 8 + t4 * 2 + j;
            int n  = n0 + cl;
            float sc = gg[n] * BN_SCALE, bv = bb[n];
            float vmax = -INFINITY, vsum = 0.f;
            #pragma unroll
            for (int mi = 0; mi < 4; mi++) {
                float va = fmaf(sc, c[mi][ni][j],     bv);
                va = (va > 0.f) ? va : expm1f(va);
                float vb = fmaf(sc, c[mi][ni][j + 2], bv);
                vb = (vb > 0.f) ? vb : expm1f(vb);
                vmax = fmaxf(vmax, fmaxf(va, vb));
                vsum += va + vb;
            }
            #pragma unroll
            for (int off = 4; off <= 16; off <<= 1) {
                vmax = fmaxf(vmax, __shfl_xor_sync(0xffffffffu, vmax, off));
                vsum += __shfl_xor_sync(0xffffffffu, vsum, off);
            }
            if (g == 0) {
                pm[(w & 1) * 128 + cl] = vmax;
                ps[(w & 1) * 128 + cl] = vsum;
            }
        }
    }
    __syncthreads();
    if (tid < 128) {
        int o = blockIdx.y * 1024 + n0 + tid;
        pomax[o] = fmaxf(pm[tid], pm[128 + tid]);
        posum[o] = ps[tid] + ps[128 + tid];
    }
}

// ---------------- fused layer-1 dist + top-k (K=3, whole cloud in smem) ----------------
__global__ void __launch_bounds__(256) dist_topk1(
        const float* __restrict__ X, int* __restrict__ out) {
    __shared__ float sx[NP], sy[NP], sz[NP], sq[NP];
    int r0 = blockIdx.x * 8;              // 8 query rows per block
    int base = r0 & ~(NP - 1);            // batch base row
    const float* xb = X + (size_t)base * 3;
    for (int i = threadIdx.x; i < NP; i += 256) {
        float a = xb[i * 3], b = xb[i * 3 + 1], cc = xb[i * 3 + 2];
        sx[i] = a; sy[i] = b; sz[i] = cc;
        sq[i] = a * a + b * b + cc * cc;
    }
    __syncthreads();
    int w = threadIdx.x >> 5, lane = threadIdx.x & 31;
    int rl = (r0 - base) + w;             // local query row
    float qx = sx[rl], qy = sy[rl], qz = sz[rl], qq = sq[rl];
    unsigned long long k[32];
    #pragma unroll
    for (int j = 0; j < 32; j++) {
        int idx = lane + j * 32;
        float t = fmaf(qx, sx[idx], fmaf(qy, sy[idx], qz * sz[idx]));
        float d = 2.f * t - qq - sq[idx];
        unsigned u = __float_as_uint(d);
        unsigned o = (u & 0x80000000u) ? ~u : (u | 0x80000000u);
        k[j] = ((unsigned long long)o << 32) | (unsigned)(1023 - idx);
    }
    unsigned long long s0 = 0, s1 = 0, s2 = 0;
    #pragma unroll
    for (int j = 0; j < 32; j++) {
        unsigned long long x = k[j];
        if (x > s0)      { s2 = s1; s1 = s0; s0 = x; }
        else if (x > s1) { s2 = s1; s1 = x; }
        else if (x > s2) { s2 = x; }
    }
    for (int it = 0; it < KNN; it++) {
        unsigned long long wv = s0;
        #pragma unroll
        for (int off = 16; off; off >>= 1) {
            unsigned long long o = __shfl_xor_sync(0xffffffffu, wv, off);
            if (o > wv) wv = o;
        }
        if (s0 == wv) {
            s0 = s1; s1 = s2; s2 = 0;
            if (s0 == 0) {
                #pragma unroll
                for (int j = 0; j < 32; j++) {
                    unsigned long long x = k[j];
                    if (x < wv) {
                        if (x > s0)      { s2 = s1; s1 = s0; s0 = x; }
                        else if (x > s1) { s2 = s1; s1 = x; }
                        else if (x > s2) { s2 = x; }
                    }
                }
            }
        }
        if (lane == 0) out[(r0 + w) * KNN + it] = base + 1023 - (int)(wv & 1023u);
    }
}

// ---------------- top-k (k=20) from dist matrix (layers 2-4) ----------------
__global__ void __launch_bounds__(256) topk_kernel(
        const float* __restrict__ D, int* __restrict__ out) {
    int warp = (blockIdx.x * blockDim.x + threadIdx.x) >> 5;
    int lane = threadIdx.x & 31;
    const float* row = D + (size_t)warp * NP;
    unsigned long long k[32];
    #pragma unroll
    for (int j = 0; j < 32; j++) {
        int idx = lane + j * 32;
        unsigned u = __float_as_uint(row[idx]);
        unsigned o = (u & 0x80000000u) ? ~u : (u | 0x80000000u);
        k[j] = ((unsigned long long)o << 32) | (unsigned)(1023 - idx);
    }
    int base = warp & ~(NP - 1);
    unsigned long long s0 = 0, s1 = 0, s2 = 0;
    #pragma unroll
    for (int j = 0; j < 32; j++) {
        unsigned long long x = k[j];
        if (x > s0)      { s2 = s1; s1 = s0; s0 = x; }
        else if (x > s1) { s2 = s1; s1 = x; }
        else if (x > s2) { s2 = x; }
    }
    for (int it = 0; it < KNN; it++) {
        unsigned long long wv = s0;
        #pragma unroll
        for (int off = 16; off; off >>= 1) {
            unsigned long long o = __shfl_xor_sync(0xffffffffu, wv, off);
            if (o > wv) wv = o;
        }
        if (s0 == wv) {
            s0 = s1; s1 = s2; s2 = 0;
            if (s0 == 0) {
                #pragma unroll
                for (int j = 0; j < 32; j++) {
                    unsigned long long x = k[j];
                    if (x < wv) {
                        if (x > s0)      { s2 = s1; s1 = s0; s0 = x; }
                        else if (x > s1) { s2 = s1; s1 = x; }
                        else if (x > s2) { s2 = x; }
                    }
                }
            }
        }
        if (lane == 0) out[warp * KNN + it] = base + 1023 - (int)(wv & 1023u);
    }
}

// ---------------- edge-conv aggregation (+ fused rowsum for next layer) ----------------
__global__ void __launch_bounds__(256) aggregate_kernel(
        const float* __restrict__ Yn, const float* __restrict__ Yc,
        int C, const int* __restrict__ idx,
        const float* __restrict__ gg, const float* __restrict__ bb,
        float* __restrict__ outp, float* __restrict__ xxout) {
    int r = blockIdx.x;
    int c = threadIdx.x;
    __shared__ int sidx[KNN];
    __shared__ float red[256];
    if (c < KNN) sidx[c] = idx[r * KNN + c];
    __syncthreads();
    float vmax = -INFINITY, vmin = INFINITY;
    #pragma unroll 4
    for (int j = 0; j < KNN; j++) {
        float v = Yn[(size_t)sidx[j] * C + c];
        vmax = fmaxf(vmax, v);
        vmin = fminf(vmin, v);
    }
    float center = Yc[(size_t)r * C + c] - Yn[(size_t)r * C + c];
    float s = gg[c] * BN_SCALE;
    float h = s * ((s >= 0.f ? vmax : vmin) + center) + bb[c];
    float e = (h > 0.f) ? h : expm1f(h);
    outp[(size_t)r * 512 + c] = e;
    if (xxout) {
        red[c] = e * e;
        __syncthreads();
        for (int st = blockDim.x >> 1; st > 0; st >>= 1) {
            if (c < st) red[c] += red[c + st];
            __syncthreads();
        }
        if (c == 0) xxout[r] = red[0];
    }
}

// ---------------- pooling combine ----------------
__global__ void __launch_bounds__(256) pool_combine(
        const float* __restrict__ pmax, const float* __restrict__ psum,
        float* __restrict__ f) {
    int t = blockIdx.x * 256 + threadIdx.x;
    if (t >= NB * 1024) return;
    int b = t >> 10, o = t & 1023;
    float m = -INFINITY, s = 0.f;
    for (int c = 0; c < 8; c++) {
        m = fmaxf(m, pmax[(b * 8 + c) * 1024 + o]);
        s += psum[(b * 8 + c) * 1024 + o];
    }
    f[b * 2048 + o] = m;
    f[b * 2048 + 1024 + o] = s * (1.f / 1024.f);
}

// ---------------- tiny MLP: one warp per output element ----------------
__global__ void __launch_bounds__(256) mlp_kernel(
        const float* __restrict__ in, int Kd,
        const float* __restrict__ W,
        const float* __restrict__ gg, const float* __restrict__ bb,
        float* __restrict__ out, int Nout, int rows, int bnelu) {
    int wid  = (blockIdx.x * blockDim.x + threadIdx.x) >> 5;
    int lane = threadIdx.x & 31;
    if (wid >= rows * Nout) return;
    int r = wid / Nout, o = wid % Nout;
    const float* a = in + (size_t)r * Kd;
    const float* w = W  + (size_t)o * Kd;
    float s = 0.f;
    for (int k = lane; k < Kd; k += 32) s += a[k] * w[k];
    #pragma unroll
    for (int off = 16; off; off >>= 1) s += __shfl_xor_sync(0xffffffffu, s, off);
    if (lane == 0) {
        float v;
        if (bnelu) {
            float sc = gg[o] * BN_SCALE;
            v = fmaf(sc, s, bb[o]);
            v = (v > 0.f) ? v : expm1f(v);
        } else {
            v = s + bb[o];
        }
        out[(size_t)r * Nout + o] = v;
    }
}

extern "C" void kernel_launch(void* const* d_in, const int* in_sizes, int n_in,
                              void* d_out, int out_size) {
    const float* x   = (const float*)d_in[0];
    const float* W1  = (const float*)d_in[1];
    const float* g1  = (const float*)d_in[2];
    const float* b1  = (const float*)d_in[3];
    const float* W2  = (const float*)d_in[4];
    const float* g2  = (const float*)d_in[5];
    const float* b2  = (const float*)d_in[6];
    const float* W3  = (const float*)d_in[7];
    const float* g3  = (const float*)d_in[8];
    const float* b3  = (const float*)d_in[9];
    const float* W4  = (const float*)d_in[10];
    const float* g4  = (const float*)d_in[11];
    const float* b4  = (const float*)d_in[12];
    const float* W5  = (const float*)d_in[13];
    const float* g5  = (const float*)d_in[14];
    const float* b5  = (const float*)d_in[15];
    const float* Wl1 = (const float*)d_in[16];
    const float* gl1 = (const float*)d_in[17];
    const float* bl1 = (const float*)d_in[18];
    const float* Wl2 = (const float*)d_in[19];
    const float* gl2 = (const float*)d_in[20];
    const float* bl2 = (const float*)d_in[21];
    const float* Wl3 = (const float*)d_in[22];
    const float* bl3 = (const float*)d_in[23];

    float *dist, *cat, *Y, *xx, *pmax, *psum, *f, *f1, *f2;
    int* idx;
    cudaGetSymbolAddress((void**)&dist, g_dist);
    cudaGetSymbolAddress((void**)&cat,  g_cat);
    cudaGetSymbolAddress((void**)&Y,    g_Y);
    cudaGetSymbolAddress((void**)&xx,   g_xx);
    cudaGetSymbolAddress((void**)&idx,  g_idx);
    cudaGetSymbolAddress((void**)&pmax, g_pmax);
    cudaGetSymbolAddress((void**)&psum, g_psum);
    cudaGetSymbolAddress((void**)&f,    g_f);
    cudaGetSymbolAddress((void**)&f1,   g_f1);
    cudaGetSymbolAddress((void**)&f2,   g_f2);

    dim3 blk(16, 16);

    // ---------- layer 1: fused dist+topk (K=3), then Y + aggregate ----------
    dist_topk1<<<NR / 8, 256>>>(x, idx);
    gemm_nt<<<dim3(1, NR / 64, 2), blk>>>(0, x, 3, 0, W1, 6, 3,
                                          Y, 64, NR * 64, 3, nullptr, 0);
    aggregate_kernel<<<NR, 64>>>(Y, Y + (size_t)NR * 64, 64, idx, g1, b1, cat + 0, xx);

    // ---------- layers 2-4 (bf16x3 m16n8k16) ----------
    struct { const float* X; int Cin; const float* W; const float* g; const float* b;
             int Cout; int off; } L[3] = {
        { cat + 0,   64,  W2, g2, b2,  64,  64 },
        { cat + 64,  64,  W3, g3, b3, 128, 128 },
        { cat + 128, 128, W4, g4, b4, 256, 256 },
    };
    for (int li = 0; li < 3; li++) {
        gemm_bf16<<<dim3(NP / 128, NP / 128, NB), 256>>>(1, NP, 1,
            L[li].X, 512, NP * 512, L[li].X, 512, NP * 512,
            dist, NP, NP * NP, L[li].Cin, xx, NP);
        topk_kernel<<<NR / 8, 256>>>(dist, idx);
        gemm_bf16<<<dim3((L[li].Cout + 127) / 128, NR / 128, 2), 256>>>(0, L[li].Cout, 0,
            L[li].X, 512, 0, L[li].W, 2 * L[li].Cin, L[li].Cin,
            Y, L[li].Cout, NR * L[li].Cout, L[li].Cin, nullptr, 0);
        aggregate_kernel<<<NR, L[li].Cout>>>(Y, Y + (size_t)NR * L[li].Cout,
            L[li].Cout, idx, L[li].g, L[li].b, cat + L[li].off,
            (li < 2) ? xx : nullptr);
    }

    // ---------- conv5: fp16 m16n8k16, fused BN/ELU + pooling partials ----------
    conv5_fp16<<<dim3(1024 / 128, NR / 128), 256>>>(cat, 512, W5, 512, 512,
                                                    g5, b5, pmax, psum);

    // ---------- pooling combine + MLP head ----------
    pool_combine<<<32, 256>>>(pmax, psum, f);
    mlp_kernel<<<512, 256>>>(f,  2048, Wl1, gl1, bl1, f1, 512, NB, 1);
    mlp_kernel<<<256, 256>>>(f1, 512,  Wl2, gl2, bl2, f2, 256, NB, 1);
    mlp_kernel<<<40,  256>>>(f2, 256,  Wl3, nullptr, bl3, (float*)d_out, 40, NB, 0);
}

// round 16
// speedup vs baseline: 1.9787x; 1.0178x over previous
#include <cuda_runtime.h>
#include <stdint.h>
#include <math.h>

#define BN_SCALE 0.99999500003749972f

#define NB 8
#define NP 1024
#define NR (NB*NP)     // 8192 rows total
#define KNN 20

// ---------------- static scratch (no allocations allowed) ----------------
__device__ __align__(16) float g_dist[(size_t)NR * NP];   // 32MB (dist, layers 2-4)
__device__ __align__(16) float g_cat [(size_t)NR * 512];  // x1|x2|x3|x4 concatenated
__device__ __align__(16) float g_Y   [(size_t)2 * NR * 256];  // Yn | Yc (z-batched)
__device__ float g_xx[NR];
__device__ int   g_idx[NR * KNN];
__device__ float g_pmax[64 * 1024];
__device__ float g_psum[64 * 1024];
__device__ float g_f [NB * 2048];
__device__ float g_f1[NB * 512];
__device__ float g_f2[NB * 256];

// ---------------- fp32 NT GEMM (layer-1 Y only, K=3) ----------------
__global__ void __launch_bounds__(256) gemm_nt(int mode,
                        const float* __restrict__ A, int lda, int batA,
                        const float* __restrict__ B, int ldb, int batB,
                        float* __restrict__ C, int ldc, int batC, int K,
                        const float* __restrict__ xx, int batX)
{
    A += (size_t)blockIdx.z * batA;
    B += (size_t)blockIdx.z * batB;
    C += (size_t)blockIdx.z * batC;
    const int m0 = blockIdx.y * 64;
    const int n0 = blockIdx.x * 64;
    __shared__ __align__(16) float As[16][64];
    __shared__ __align__(16) float Bs[16][64];
    const int tx = threadIdx.x, ty = threadIdx.y;
    const int t = ty * 16 + tx;
    const int lm = t >> 2;
    const int lk = (t & 3) * 4;
    float acc[4][4] = {};
    for (int k0 = 0; k0 < K; k0 += 16) {
        #pragma unroll
        for (int u = 0; u < 4; u++) {
            int kk = lk + u;
            As[kk][lm] = (k0 + kk < K) ? A[(size_t)(m0 + lm) * lda + k0 + kk] : 0.f;
            Bs[kk][lm] = (k0 + kk < K) ? B[(size_t)(n0 + lm) * ldb + k0 + kk] : 0.f;
        }
        __syncthreads();
        #pragma unroll
        for (int kk = 0; kk < 16; kk++) {
            float4 a4 = *reinterpret_cast<const float4*>(&As[kk][ty * 4]);
            float4 b4 = *reinterpret_cast<const float4*>(&Bs[kk][tx * 4]);
            float a[4] = {a4.x, a4.y, a4.z, a4.w};
            float b[4] = {b4.x, b4.y, b4.z, b4.w};
            #pragma unroll
            for (int i = 0; i < 4; i++)
                #pragma unroll
                for (int j = 0; j < 4; j++)
                    acc[i][j] = fmaf(a[i], b[j], acc[i][j]);
        }
        __syncthreads();
    }
    #pragma unroll
    for (int i = 0; i < 4; i++) {
        int m = m0 + ty * 4 + i;
        int n = n0 + tx * 4;
        float4 v; float* vp = &v.x;
        if (mode == 1) {
            float xm = xx[batX * blockIdx.z + m];
            #pragma unroll
            for (int j = 0; j < 4; j++)
                vp[j] = 2.f * acc[i][j] - xm - xx[batX * blockIdx.z + n + j];
        } else {
            #pragma unroll
            for (int j = 0; j < 4; j++) vp[j] = acc[i][j];
        }
        *reinterpret_cast<float4*>(&C[(size_t)m * ldc + n]) = v;
    }
}

// ---------------- ldmatrix helper ----------------
#define LDSM4(r0, r1, r2, r3, addr)                                            \
    asm volatile("ldmatrix.sync.aligned.m8n8.x4.shared.b16 {%0,%1,%2,%3}, [%4];" \
                 : "=r"(r0), "=r"(r1), "=r"(r2), "=r"(r3) : "r"(addr))

// ---------------- bf16x3 mma.sync m16n8k16 NT GEMM (dist / Y, layers 2-4) ----------------
__device__ __forceinline__ unsigned pkbf(float a, float b) {   // lo half=a, hi half=b
    unsigned r; asm("cvt.rn.bf16x2.f32 %0, %1, %2;" : "=r"(r) : "f"(b), "f"(a));
    return r;
}
__device__ __forceinline__ void split4(float4 v, unsigned& h0, unsigned& h1,
                                       unsigned& l0, unsigned& l1) {
    h0 = pkbf(v.x, v.y); h1 = pkbf(v.z, v.w);
    float hx = __uint_as_float(h0 << 16), hy = __uint_as_float(h0 & 0xFFFF0000u);
    float hz = __uint_as_float(h1 << 16), hw = __uint_as_float(h1 & 0xFFFF0000u);
    l0 = pkbf(v.x - hx, v.y - hy);
    l1 = pkbf(v.z - hz, v.w - hw);
}
#define MMA_BF16(c, a0,a1,a2,a3, b0,b1)                                        \
    asm volatile("mma.sync.aligned.m16n8k16.row.col.f32.bf16.bf16.f32 "         \
                 "{%0,%1,%2,%3}, {%4,%5,%6,%7}, {%8,%9}, {%0,%1,%2,%3};"        \
                 : "+f"(c[0]), "+f"(c[1]), "+f"(c[2]), "+f"(c[3])               \
                 : "r"(a0), "r"(a1), "r"(a2), "r"(a3), "r"(b0), "r"(b1))

__global__ void __launch_bounds__(256) gemm_bf16(int mode, int N, int sym,
        const float* __restrict__ A, int lda, int batA,
        const float* __restrict__ B, int ldb, int batB,
        float* __restrict__ C, int ldc, int batC, int K,
        const float* __restrict__ xx, int batX)
{
    if (sym && blockIdx.x > blockIdx.y) return;   // lower triangle only
    A += (size_t)blockIdx.z * batA;
    B += (size_t)blockIdx.z * batB;
    C += (size_t)blockIdx.z * batC;
    const float* xb = xx ? (xx + (size_t)batX * blockIdx.z) : xx;

    const int m0 = blockIdx.y * 128;
    const int n0 = blockIdx.x * 128;

    __shared__ __align__(16) uint32_t SM[2][4][128][12];   // Ah,Al,Bh,Bl; 48KB

    const int tid = threadIdx.x;
    const int w  = tid >> 5, l = tid & 31;
    const int g  = l >> 2,  t4 = l & 3;
    const int wm = (w & 1) * 64;
    const int wn = (w >> 1) * 32;
    const int lr = tid >> 2;
    const int lk = (tid & 3) * 4;
    const int kp = (tid & 3) * 2;
    const int row_off = (l & 7) + ((l >> 3) & 1) * 8;   // ldmatrix lane->row
    const int kchunk  = (l >> 4) * 4;                   // ldmatrix lane->16B chunk

    float c[4][4][4];
    #pragma unroll
    for (int i = 0; i < 4; i++)
        #pragma unroll
        for (int j = 0; j < 4; j++)
            #pragma unroll
            for (int q = 0; q < 4; q++) c[i][j][q] = 0.f;

    const float4 z4 = {0.f, 0.f, 0.f, 0.f};
    float4 ra0, ra1, rb0, rb1;

    {
        const float* Ap = A + (size_t)(m0 + lr) * lda + lk;
        ra0 = *(const float4*)Ap;
        ra1 = *(const float4*)(Ap + (size_t)64 * lda);
        int nr0 = n0 + lr, nr1 = nr0 + 64;
        rb0 = (nr0 < N) ? *(const float4*)(B + (size_t)nr0 * ldb + lk) : z4;
        rb1 = (nr1 < N) ? *(const float4*)(B + (size_t)nr1 * ldb + lk) : z4;
    }

    const int T = K / 16;
    int p = 0;
    for (int t = 0; t < T; t++) {
        __syncthreads();
        {
            unsigned h0, h1, l0, l1;
            split4(ra0, h0, h1, l0, l1);
            *(uint2*)&SM[p][0][lr][kp] = make_uint2(h0, h1);
            *(uint2*)&SM[p][1][lr][kp] = make_uint2(l0, l1);
            split4(ra1, h0, h1, l0, l1);
            *(uint2*)&SM[p][0][lr + 64][kp] = make_uint2(h0, h1);
            *(uint2*)&SM[p][1][lr + 64][kp] = make_uint2(l0, l1);
            split4(rb0, h0, h1, l0, l1);
            *(uint2*)&SM[p][2][lr][kp] = make_uint2(h0, h1);
            *(uint2*)&SM[p][3][lr][kp] = make_uint2(l0, l1);
            split4(rb1, h0, h1, l0, l1);
            *(uint2*)&SM[p][2][lr + 64][kp] = make_uint2(h0, h1);
            *(uint2*)&SM[p][3][lr + 64][kp] = make_uint2(l0, l1);
        }
        __syncthreads();
        if (t + 1 < T) {
            int k0 = (t + 1) * 16;
            const float* Ap = A + (size_t)(m0 + lr) * lda + k0 + lk;
            ra0 = *(const float4*)Ap;
            ra1 = *(const float4*)(Ap + (size_t)64 * lda);
            int nr0 = n0 + lr, nr1 = nr0 + 64;
            rb0 = (nr0 < N) ? *(const float4*)(B + (size_t)nr0 * ldb + k0 + lk) : z4;
            rb1 = (nr1 < N) ? *(const float4*)(B + (size_t)nr1 * ldb + k0 + lk) : z4;
        }
        {
            unsigned ah[4][4], al[4][4], bh[4][2], bl[4][2];
            #pragma unroll
            for (int mi = 0; mi < 4; mi++) {
                uint32_t aH = (uint32_t)__cvta_generic_to_shared(
                    &SM[p][0][wm + mi * 16 + row_off][kchunk]);
                uint32_t aL = (uint32_t)__cvta_generic_to_shared(
                    &SM[p][1][wm + mi * 16 + row_off][kchunk]);
                LDSM4(ah[mi][0], ah[mi][1], ah[mi][2], ah[mi][3], aH);
                LDSM4(al[mi][0], al[mi][1], al[mi][2], al[mi][3], aL);
            }
            #pragma unroll
            for (int pr = 0; pr < 2; pr++) {
                uint32_t bH = (uint32_t)__cvta_generic_to_shared(
                    &SM[p][2][wn + pr * 16 + row_off][kchunk]);
                uint32_t bL = (uint32_t)__cvta_generic_to_shared(
                    &SM[p][3][wn + pr * 16 + row_off][kchunk]);
                unsigned r0, r1, r2, r3;
                LDSM4(r0, r1, r2, r3, bH);
                bh[2 * pr][0] = r0; bh[2 * pr + 1][0] = r1;
                bh[2 * pr][1] = r2; bh[2 * pr + 1][1] = r3;
                LDSM4(r0, r1, r2, r3, bL);
                bl[2 * pr][0] = r0; bl[2 * pr + 1][0] = r1;
                bl[2 * pr][1] = r2; bl[2 * pr + 1][1] = r3;
            }
            #pragma unroll
            for (int mi = 0; mi < 4; mi++)
                #pragma unroll
                for (int ni = 0; ni < 4; ni++) {
                    float* cc = c[mi][ni];
                    MMA_BF16(cc, ah[mi][0], ah[mi][1], ah[mi][2], ah[mi][3],
                                 bl[ni][0], bl[ni][1]);
                    MMA_BF16(cc, al[mi][0], al[mi][1], al[mi][2], al[mi][3],
                                 bh[ni][0], bh[ni][1]);
                    MMA_BF16(cc, ah[mi][0], ah[mi][1], ah[mi][2], ah[mi][3],
                                 bh[ni][0], bh[ni][1]);
                }
        }
        p ^= 1;
    }

    // ---- normal epilogue ----
    #pragma unroll
    for (int mi = 0; mi < 4; mi++) {
        int r0 = m0 + wm + mi * 16 + g;
        int r1 = r0 + 8;
        float xm0 = 0.f, xm1 = 0.f;
        if (mode == 1) { xm0 = xb[r0]; xm1 = xb[r1]; }
        #pragma unroll
        for (int ni = 0; ni < 4; ni++) {
            int n = n0 + wn + ni * 8 + t4 * 2;
            if (n < N) {
                float v0 = c[mi][ni][0], v1 = c[mi][ni][1];
                float v2 = c[mi][ni][2], v3 = c[mi][ni][3];
                if (mode == 1) {
                    float xn0 = xb[n], xn1 = xb[n + 1];
                    v0 = 2.f * v0 - xm0 - xn0;  v1 = 2.f * v1 - xm0 - xn1;
                    v2 = 2.f * v2 - xm1 - xn0;  v3 = 2.f * v3 - xm1 - xn1;
                }
                float2 p0 = {v0, v1}, p1 = {v2, v3};
                *(float2*)&C[(size_t)r0 * ldc + n] = p0;
                *(float2*)&C[(size_t)r1 * ldc + n] = p1;
            }
        }
    }

    // ---- mirror epilogue (sym, strictly lower blocks) ----
    if (sym && blockIdx.x < blockIdx.y) {
        float (*st)[132] = reinterpret_cast<float(*)[132]>(&SM[0][0][0][0]);
        #pragma unroll 1
        for (int s = 0; s < 4; s++) {
            __syncthreads();
            #pragma unroll
            for (int mi = 0; mi < 4; mi++) {
                int r0l = wm + mi * 16 + g;
                int r0 = m0 + r0l, r1 = r0 + 8;
                int n  = n0 + wn + s * 8 + t4 * 2;
                float xm0 = xb[r0], xm1 = xb[r1];
                float xn0 = xb[n],  xn1 = xb[n + 1];
                float v0 = 2.f * c[mi][s][0] - xm0 - xn0;
                float v1 = 2.f * c[mi][s][1] - xm0 - xn1;
                float v2 = 2.f * c[mi][s][2] - xm1 - xn0;
                float v3 = 2.f * c[mi][s][3] - xm1 - xn1;
                int cl = (w >> 1) * 8 + t4 * 2;
                st[cl    ][r0l]     = v0;
                st[cl + 1][r0l]     = v1;
                st[cl    ][r0l + 8] = v2;
                st[cl + 1][r0l + 8] = v3;
            }
            __syncthreads();
            int rsel = tid >> 3;
            int wnq = rsel >> 3, off = rsel & 7;
            int nl = wnq * 32 + s * 8 + off;
            int colm = (tid & 7) * 16;
            float* dst = &C[(size_t)(n0 + nl) * ldc + m0 + colm];
            const float* src = &st[rsel][colm];
            #pragma unroll
            for (int q = 0; q < 4; q++)
                *(float4*)(dst + q * 4) = *(const float4*)(src + q * 4);
        }
    }
}

// ---------------- fp16 single m16n8k16 conv5 + fused BN/ELU + pooling ----------------
__device__ __forceinline__ unsigned pkhf(float a, float b) {   // lo half=a, hi half=b
    unsigned r; asm("cvt.rn.f16x2.f32 %0, %1, %2;" : "=r"(r) : "f"(b), "f"(a));
    return r;
}
#define MMA_FP16(c, a0,a1,a2,a3, b0,b1)                                        \
    asm volatile("mma.sync.aligned.m16n8k16.row.col.f32.f16.f16.f32 "           \
                 "{%0,%1,%2,%3}, {%4,%5,%6,%7}, {%8,%9}, {%0,%1,%2,%3};"        \
                 : "+f"(c[0]), "+f"(c[1]), "+f"(c[2]), "+f"(c[3])               \
                 : "r"(a0), "r"(a1), "r"(a2), "r"(a3), "r"(b0), "r"(b1))

__global__ void __launch_bounds__(256) conv5_fp16(
        const float* __restrict__ A, int lda,
        const float* __restrict__ B, int ldb, int K,
        const float* __restrict__ gg, const float* __restrict__ bb,
        float* __restrict__ pomax, float* __restrict__ posum)
{
    const int m0 = blockIdx.y * 128;
    const int n0 = blockIdx.x * 128;

    __shared__ __align__(16) uint32_t SM[2][2][128][12];   // A,B fp16 pairs; 24KB

    const int tid = threadIdx.x;
    const int w  = tid >> 5, l = tid & 31;
    const int g  = l >> 2,  t4 = l & 3;
    const int wm = (w & 1) * 64;
    const int wn = (w >> 1) * 32;
    const int lr = tid >> 2;
    const int lk = (tid & 3) * 4;
    const int kp = (tid & 3) * 2;
    const int row_off = (l & 7) + ((l >> 3) & 1) * 8;
    const int kchunk  = (l >> 4) * 4;

    float c[4][4][4];
    #pragma unroll
    for (int i = 0; i < 4; i++)
        #pragma unroll
        for (int j = 0; j < 4; j++)
            #pragma unroll
            for (int q = 0; q < 4; q++) c[i][j][q] = 0.f;

    float4 ra0, ra1, rb0, rb1;
    {
        const float* Ap = A + (size_t)(m0 + lr) * lda + lk;
        ra0 = *(const float4*)Ap;
        ra1 = *(const float4*)(Ap + (size_t)64 * lda);
        const float* Bp = B + (size_t)(n0 + lr) * ldb + lk;
        rb0 = *(const float4*)Bp;
        rb1 = *(const float4*)(Bp + (size_t)64 * ldb);
    }

    const int T = K / 16;
    int p = 0;
    for (int t = 0; t < T; t++) {
        __syncthreads();
        *(uint2*)&SM[p][0][lr][kp]      = make_uint2(pkhf(ra0.x, ra0.y), pkhf(ra0.z, ra0.w));
        *(uint2*)&SM[p][0][lr + 64][kp] = make_uint2(pkhf(ra1.x, ra1.y), pkhf(ra1.z, ra1.w));
        *(uint2*)&SM[p][1][lr][kp]      = make_uint2(pkhf(rb0.x, rb0.y), pkhf(rb0.z, rb0.w));
        *(uint2*)&SM[p][1][lr + 64][kp] = make_uint2(pkhf(rb1.x, rb1.y), pkhf(rb1.z, rb1.w));
        __syncthreads();
        if (t + 1 < T) {
            int k0 = (t + 1) * 16;
            const float* Ap = A + (size_t)(m0 + lr) * lda + k0 + lk;
            ra0 = *(const float4*)Ap;
            ra1 = *(const float4*)(Ap + (size_t)64 * lda);
            const float* Bp = B + (size_t)(n0 + lr) * ldb + k0 + lk;
            rb0 = *(const float4*)Bp;
            rb1 = *(const float4*)(Bp + (size_t)64 * ldb);
        }
        {
            unsigned ah[4][4], bh[4][2];
            #pragma unroll
            for (int mi = 0; mi < 4; mi++) {
                uint32_t aH = (uint32_t)__cvta_generic_to_shared(
                    &SM[p][0][wm + mi * 16 + row_off][kchunk]);
                LDSM4(ah[mi][0], ah[mi][1], ah[mi][2], ah[mi][3], aH);
            }
            #pragma unroll
            for (int pr = 0; pr < 2; pr++) {
                uint32_t bH = (uint32_t)__cvta_generic_to_shared(
                    &SM[p][1][wn + pr * 16 + row_off][kchunk]);
                unsigned r0, r1, r2, r3;
                LDSM4(r0, r1, r2, r3, bH);
                bh[2 * pr][0] = r0; bh[2 * pr + 1][0] = r1;
                bh[2 * pr][1] = r2; bh[2 * pr + 1][1] = r3;
            }
            #pragma unroll
            for (int mi = 0; mi < 4; mi++)
                #pragma unroll
                for (int ni = 0; ni < 4; ni++)
                    MMA_FP16(c[mi][ni], ah[mi][0], ah[mi][1], ah[mi][2], ah[mi][3],
                             bh[ni][0], bh[ni][1]);
        }
        p ^= 1;
    }

    // fused BN/ELU + max/sum pooling over the block's 128 rows
    __syncthreads();
    float* pm = (float*)&SM[0][0][0][0];   // [2][128]
    float* ps = pm + 256;
    #pragma unroll
    for (int ni = 0; ni < 4; ni++) {
        #pragma unroll
        for (int j = 0; j < 2; j++) {
            int cl = wn + ni * 8 + t4 * 2 + j;
            int n  = n0 + cl;
            float sc = gg[n] * BN_SCALE, bv = bb[n];
            float vmax = -INFINITY, vsum = 0.f;
            #pragma unroll
            for (int mi = 0; mi < 4; mi++) {
                float va = fmaf(sc, c[mi][ni][j],     bv);
                va = (va > 0.f) ? va : expm1f(va);
                float vb = fmaf(sc, c[mi][ni][j + 2], bv);
                vb = (vb > 0.f) ? vb : expm1f(vb);
                vmax = fmaxf(vmax, fmaxf(va, vb));
                vsum += va + vb;
            }
            #pragma unroll
            for (int off = 4; off <= 16; off <<= 1) {
                vmax = fmaxf(vmax, __shfl_xor_sync(0xffffffffu, vmax, off));
                vsum += __shfl_xor_sync(0xffffffffu, vsum, off);
            }
            if (g == 0) {
                pm[(w & 1) * 128 + cl] = vmax;
                ps[(w & 1) * 128 + cl] = vsum;
            }
        }
    }
    __syncthreads();
    if (tid < 128) {
        int o = blockIdx.y * 1024 + n0 + tid;
        pomax[o] = fmaxf(pm[tid], pm[128 + tid]);
        posum[o] = ps[tid] + ps[128 + tid];
    }
}

// ---------------- fused layer-1 dist + top-k (K=3, whole cloud in smem) ----------------
__global__ void __launch_bounds__(256) dist_topk1(
        const float* __restrict__ X, int* __restrict__ out) {
    __shared__ float sx[NP], sy[NP], sz[NP], sq[NP];
    int r0 = blockIdx.x * 8;              // 8 query rows per block
    int base = r0 & ~(NP - 1);            // batch base row
    const float* xb = X + (size_t)base * 3;
    for (int i = threadIdx.x; i < NP; i += 256) {
        float a = xb[i * 3], b = xb[i * 3 + 1], cc = xb[i * 3 + 2];
        sx[i] = a; sy[i] = b; sz[i] = cc;
        sq[i] = a * a + b * b + cc * cc;
    }
    __syncthreads();
    int w = threadIdx.x >> 5, lane = threadIdx.x & 31;
    int rl = (r0 - base) + w;             // local query row
    float qx = sx[rl], qy = sy[rl], qz = sz[rl], qq = sq[rl];
    unsigned long long k[32];
    #pragma unroll
    for (int j = 0; j < 32; j++) {
        int idx = lane + j * 32;
        float t = fmaf(qx, sx[idx], fmaf(qy, sy[idx], qz * sz[idx]));
        float d = 2.f * t - qq - sq[idx];
        unsigned u = __float_as_uint(d);
        unsigned o = (u & 0x80000000u) ? ~u : (u | 0x80000000u);
        k[j] = ((unsigned long long)o << 32) | (unsigned)(1023 - idx);
    }
    unsigned long long s0 = 0, s1 = 0, s2 = 0;
    #pragma unroll
    for (int j = 0; j < 32; j++) {
        unsigned long long x = k[j];
        if (x > s0)      { s2 = s1; s1 = s0; s0 = x; }
        else if (x > s1) { s2 = s1; s1 = x; }
        else if (x > s2) { s2 = x; }
    }
    for (int it = 0; it < KNN; it++) {
        unsigned long long wv = s0;
        #pragma unroll
        for (int off = 16; off; off >>= 1) {
            unsigned long long o = __shfl_xor_sync(0xffffffffu, wv, off);
            if (o > wv) wv = o;
        }
        if (s0 == wv) {
            s0 = s1; s1 = s2; s2 = 0;
            if (s0 == 0) {
                #pragma unroll
                for (int j = 0; j < 32; j++) {
                    unsigned long long x = k[j];
                    if (x < wv) {
                        if (x > s0)      { s2 = s1; s1 = s0; s0 = x; }
                        else if (x > s1) { s2 = s1; s1 = x; }
                        else if (x > s2) { s2 = x; }
                    }
                }
            }
        }
        if (lane == 0) out[(r0 + w) * KNN + it] = base + 1023 - (int)(wv & 1023u);
    }
}

// ---------------- top-k (k=20) from dist matrix (layers 2-4) ----------------
__global__ void __launch_bounds__(256) topk_kernel(
        const float* __restrict__ D, int* __restrict__ out) {
    int warp = (blockIdx.x * blockDim.x + threadIdx.x) >> 5;
    int lane = threadIdx.x & 31;
    const float* row = D + (size_t)warp * NP;
    unsigned long long k[32];
    #pragma unroll
    for (int j = 0; j < 32; j++) {
        int idx = lane + j * 32;
        unsigned u = __float_as_uint(row[idx]);
        unsigned o = (u & 0x80000000u) ? ~u : (u | 0x80000000u);
        k[j] = ((unsigned long long)o << 32) | (unsigned)(1023 - idx);
    }
    int base = warp & ~(NP - 1);
    unsigned long long s0 = 0, s1 = 0, s2 = 0;
    #pragma unroll
    for (int j = 0; j < 32; j++) {
        unsigned long long x = k[j];
        if (x > s0)      { s2 = s1; s1 = s0; s0 = x; }
        else if (x > s1) { s2 = s1; s1 = x; }
        else if (x > s2) { s2 = x; }
    }
    for (int it = 0; it < KNN; it++) {
        unsigned long long wv = s0;
        #pragma unroll
        for (int off = 16; off; off >>= 1) {
            unsigned long long o = __shfl_xor_sync(0xffffffffu, wv, off);
            if (o > wv) wv = o;
        }
        if (s0 == wv) {
            s0 = s1; s1 = s2; s2 = 0;
            if (s0 == 0) {
                #pragma unroll
                for (int j = 0; j < 32; j++) {
                    unsigned long long x = k[j];
                    if (x < wv) {
                        if (x > s0)      { s2 = s1; s1 = s0; s0 = x; }
                        else if (x > s1) { s2 = s1; s1 = x; }
                        else if (x > s2) { s2 = x; }
                    }
                }
            }
        }
        if (lane == 0) out[warp * KNN + it] = base + 1023 - (int)(wv & 1023u);
    }
}

// ---------------- edge-conv aggregation (+ fused rowsum for next layer) ----------------
__global__ void __launch_bounds__(256) aggregate_kernel(
        const float* __restrict__ Yn, const float* __restrict__ Yc,
        int C, const int* __restrict__ idx,
        const float* __restrict__ gg, const float* __restrict__ bb,
        float* __restrict__ outp, float* __restrict__ xxout) {
    int r = blockIdx.x;
    int c = threadIdx.x;
    __shared__ int sidx[KNN];
    __shared__ float red[256];
    if (c < KNN) sidx[c] = idx[r * KNN + c];
    __syncthreads();
    float vmax = -INFINITY, vmin = INFINITY;
    #pragma unroll 4
    for (int j = 0; j < KNN; j++) {
        float v = Yn[(size_t)sidx[j] * C + c];
        vmax = fmaxf(vmax, v);
        vmin = fminf(vmin, v);
    }
    float center = Yc[(size_t)r * C + c] - Yn[(size_t)r * C + c];
    float s = gg[c] * BN_SCALE;
    float h = s * ((s >= 0.f ? vmax : vmin) + center) + bb[c];
    float e = (h > 0.f) ? h : expm1f(h);
    outp[(size_t)r * 512 + c] = e;
    if (xxout) {
        red[c] = e * e;
        __syncthreads();
        for (int st = blockDim.x >> 1; st > 0; st >>= 1) {
            if (c < st) red[c] += red[c + st];
            __syncthreads();
        }
        if (c == 0) xxout[r] = red[0];
    }
}

// ---------------- pooling combine ----------------
__global__ void __launch_bounds__(256) pool_combine(
        const float* __restrict__ pmax, const float* __restrict__ psum,
        float* __restrict__ f) {
    int t = blockIdx.x * 256 + threadIdx.x;
    if (t >= NB * 1024) return;
    int b = t >> 10, o = t & 1023;
    float m = -INFINITY, s = 0.f;
    for (int c = 0; c < 8; c++) {
        m = fmaxf(m, pmax[(b * 8 + c) * 1024 + o]);
        s += psum[(b * 8 + c) * 1024 + o];
    }
    f[b * 2048 + o] = m;
    f[b * 2048 + 1024 + o] = s * (1.f / 1024.f);
}

// ---------------- tiny MLP: one warp per output element ----------------
__global__ void __launch_bounds__(256) mlp_kernel(
        const float* __restrict__ in, int Kd,
        const float* __restrict__ W,
        const float* __restrict__ gg, const float* __restrict__ bb,
        float* __restrict__ out, int Nout, int rows, int bnelu) {
    int wid  = (blockIdx.x * blockDim.x + threadIdx.x) >> 5;
    int lane = threadIdx.x & 31;
    if (wid >= rows * Nout) return;
    int r = wid / Nout, o = wid % Nout;
    const float* a = in + (size_t)r * Kd;
    const float* w = W  + (size_t)o * Kd;
    float s = 0.f;
    for (int k = lane; k < Kd; k += 32) s += a[k] * w[k];
    #pragma unroll
    for (int off = 16; off; off >>= 1) s += __shfl_xor_sync(0xffffffffu, s, off);
    if (lane == 0) {
        float v;
        if (bnelu) {
            float sc = gg[o] * BN_SCALE;
            v = fmaf(sc, s, bb[o]);
            v = (v > 0.f) ? v : expm1f(v);
        } else {
            v = s + bb[o];
        }
        out[(size_t)r * Nout + o] = v;
    }
}

extern "C" void kernel_launch(void* const* d_in, const int* in_sizes, int n_in,
                              void* d_out, int out_size) {
    const float* x   = (const float*)d_in[0];
    const float* W1  = (const float*)d_in[1];
    const float* g1  = (const float*)d_in[2];
    const float* b1  = (const float*)d_in[3];
    const float* W2  = (const float*)d_in[4];
    const float* g2  = (const float*)d_in[5];
    const float* b2  = (const float*)d_in[6];
    const float* W3  = (const float*)d_in[7];
    const float* g3  = (const float*)d_in[8];
    const float* b3  = (const float*)d_in[9];
    const float* W4  = (const float*)d_in[10];
    const float* g4  = (const float*)d_in[11];
    const float* b4  = (const float*)d_in[12];
    const float* W5  = (const float*)d_in[13];
    const float* g5  = (const float*)d_in[14];
    const float* b5  = (const float*)d_in[15];
    const float* Wl1 = (const float*)d_in[16];
    const float* gl1 = (const float*)d_in[17];
    const float* bl1 = (const float*)d_in[18];
    const float* Wl2 = (const float*)d_in[19];
    const float* gl2 = (const float*)d_in[20];
    const float* bl2 = (const float*)d_in[21];
    const float* Wl3 = (const float*)d_in[22];
    const float* bl3 = (const float*)d_in[23];

    float *dist, *cat, *Y, *xx, *pmax, *psum, *f, *f1, *f2;
    int* idx;
    cudaGetSymbolAddress((void**)&dist, g_dist);
    cudaGetSymbolAddress((void**)&cat,  g_cat);
    cudaGetSymbolAddress((void**)&Y,    g_Y);
    cudaGetSymbolAddress((void**)&xx,   g_xx);
    cudaGetSymbolAddress((void**)&idx,  g_idx);
    cudaGetSymbolAddress((void**)&pmax, g_pmax);
    cudaGetSymbolAddress((void**)&psum, g_psum);
    cudaGetSymbolAddress((void**)&f,    g_f);
    cudaGetSymbolAddress((void**)&f1,   g_f1);
    cudaGetSymbolAddress((void**)&f2,   g_f2);

    dim3 blk(16, 16);

    // ---------- layer 1: fused dist+topk (K=3), then Y + aggregate ----------
    dist_topk1<<<NR / 8, 256>>>(x, idx);
    gemm_nt<<<dim3(1, NR / 64, 2), blk>>>(0, x, 3, 0, W1, 6, 3,
                                          Y, 64, NR * 64, 3, nullptr, 0);
    aggregate_kernel<<<NR, 64>>>(Y, Y + (size_t)NR * 64, 64, idx, g1, b1, cat + 0, xx);

    // ---------- layers 2-4 (bf16x3 m16n8k16, ldmatrix fragments) ----------
    struct { const float* X; int Cin; const float* W; const float* g; const float* b;
             int Cout; int off; } L[3] = {
        { cat + 0,   64,  W2, g2, b2,  64,  64 },
        { cat + 64,  64,  W3, g3, b3, 128, 128 },
        { cat + 128, 128, W4, g4, b4, 256, 256 },
    };
    for (int li = 0; li < 3; li++) {
        gemm_bf16<<<dim3(NP / 128, NP / 128, NB), 256>>>(1, NP, 1,
            L[li].X, 512, NP * 512, L[li].X, 512, NP * 512,
            dist, NP, NP * NP, L[li].Cin, xx, NP);
        topk_kernel<<<NR / 8, 256>>>(dist, idx);
        gemm_bf16<<<dim3((L[li].Cout + 127) / 128, NR / 128, 2), 256>>>(0, L[li].Cout, 0,
            L[li].X, 512, 0, L[li].W, 2 * L[li].Cin, L[li].Cin,
            Y, L[li].Cout, NR * L[li].Cout, L[li].Cin, nullptr, 0);
        aggregate_kernel<<<NR, L[li].Cout>>>(Y, Y + (size_t)NR * L[li].Cout,
            L[li].Cout, idx, L[li].g, L[li].b, cat + L[li].off,
            (li < 2) ? xx : nullptr);
    }

    // ---------- conv5: fp16 m16n8k16 (ldmatrix), fused BN/ELU + pooling ----------
    conv5_fp16<<<dim3(1024 / 128, NR / 128), 256>>>(cat, 512, W5, 512, 512,
                                                    g5, b5, pmax, psum);

    // ---------- pooling combine + MLP head ----------
    pool_combine<<<32, 256>>>(pmax, psum, f);
    mlp_kernel<<<512, 256>>>(f,  2048, Wl1, gl1, bl1, f1, 512, NB, 1);
    mlp_kernel<<<256, 256>>>(f1, 512,  Wl2, gl2, bl2, f2, 256, NB, 1);
    mlp_kernel<<<40,  256>>>(f2, 256,  Wl3, nullptr, bl3, (float*)d_out, 40, NB, 0);
}